// round 9
// baseline (speedup 1.0000x reference)
#include <cuda_runtime.h>
#include <math.h>

// Problem constants
#define B_     16
#define HH     28
#define WW     28
#define HW     784
#define C_ALL  3072
#define C4     2048
#define C3     1024
#define H4     14
#define HW4    196
#define NL     9
#define NK     2000

#define NCH4   32   // l4 chunks (64 ch each) over 2048, contraction at 14x14
#define NCH3   16   // l3 chunks (64 ch each) over 1024, contraction at 28x28
#define NCHT   (NCH4 + NCH3)

// Output layout: class_scores (16*2000), maps (16*9*784), all_features (16*3072*9)
#define CLS_OFF  0
#define MAPS_OFF (B_*NK)                  // 32000
#define FEAT_OFF (MAPS_OFF + B_*NL*HW)    // 144896

// Scratch (static __device__ arrays: allocation-free)
__device__ float g_asq[NL];
__device__ float g_p4[(size_t)B_*NCH4*NL*HW4];        // 3.6 MB partial ab4 [b][ch][l][q]
__device__ float g_part3[(size_t)NCH3*B_*NL*HW];      // 7.1 MB partial ab3 [ch][b][l][px]
__device__ float g_ab4[(size_t)B_*NL*HW4];            // summed ab4 (14x14)
__device__ float g_md[(size_t)B_*NL*HW4];             // adjoint-downsampled maps
__device__ float g_modavg[(size_t)C_ALL*B_];          // [c][b]

// ---------------------------------------------------------------------------
// K1: fused landmark-logit contraction over 64-channel chunks (+asq column).
//  chunk <  NCH4 : ab4 partials at 14x14 (direct coalesced LDG, no staging)
//  chunk <  NCHT : ab3 partials at 28x28 (float4 per thread)
//  chunk == NCHT : a_sq[l] = ||W_land[l]||^2 (b = landmark index)
// Weights staged transposed [c][12] -> 2xLDS.128 + LDS per channel.
// ---------------------------------------------------------------------------
__global__ __launch_bounds__(196) void k_ab(const float* __restrict__ l3,
                                            const float* __restrict__ l4,
                                            const float* __restrict__ Wl) {
    __shared__ float sWt[64 * 12];      // 3 KB, [c][l] padded to 12

    int b = blockIdx.y, chunk = blockIdx.x, tid = threadIdx.x;

    if (chunk == NCHT) {
        // ---- asq: one block per landmark (b = l), first 192 threads ----
        __shared__ float sRed[6];
        if (b >= NL) return;
        if (tid < 192) {
            int lane = tid & 31, warp = tid >> 5;
            float s = 0.f;
            for (int i = tid; i < C_ALL; i += 192) {
                float w = Wl[b * C_ALL + i];
                s = fmaf(w, w, s);
            }
            #pragma unroll
            for (int o = 16; o; o >>= 1) s += __shfl_xor_sync(0xffffffffu, s, o);
            if (lane == 0) sRed[warp] = s;
        }
        __syncthreads();
        if (tid == 0) {
            float t = 0.f;
            #pragma unroll
            for (int w = 0; w < 6; w++) t += sRed[w];
            g_asq[b] = t;
        }
        return;
    }

    if (chunk < NCH4) {
        int c0 = chunk * 64;
        for (int i = tid; i < 64 * NL; i += 196) {
            int c = i / 9, l = i - c * 9;
            sWt[c * 12 + l] = Wl[l * C_ALL + c0 + c];
        }
        const float* l4b = l4 + ((size_t)b * C4 + c0) * HW4 + tid;

        float acc[NL];
        #pragma unroll
        for (int l = 0; l < NL; l++) acc[l] = 0.f;

        __syncthreads();
        #pragma unroll 8
        for (int c = 0; c < 64; c++) {
            float x = l4b[(size_t)c * HW4];        // coalesced LDG.32
            float4 wa = *(const float4*)&sWt[c * 12];
            float4 wb = *(const float4*)&sWt[c * 12 + 4];
            float  w8 = sWt[c * 12 + 8];
            acc[0] = fmaf(wa.x, x, acc[0]);
            acc[1] = fmaf(wa.y, x, acc[1]);
            acc[2] = fmaf(wa.z, x, acc[2]);
            acc[3] = fmaf(wa.w, x, acc[3]);
            acc[4] = fmaf(wb.x, x, acc[4]);
            acc[5] = fmaf(wb.y, x, acc[5]);
            acc[6] = fmaf(wb.z, x, acc[6]);
            acc[7] = fmaf(wb.w, x, acc[7]);
            acc[8] = fmaf(w8,   x, acc[8]);
        }
        float* dst = g_p4 + ((size_t)(b * NCH4 + chunk) * NL) * HW4 + tid;
        #pragma unroll
        for (int l = 0; l < NL; l++) dst[(size_t)l * HW4] = acc[l];
    } else {
        int ch3 = chunk - NCH4;
        int c0 = ch3 * 64;
        for (int i = tid; i < 64 * NL; i += 196) {
            int c = i / 9, l = i - c * 9;
            sWt[c * 12 + l] = Wl[l * C_ALL + C4 + c0 + c];
        }
        int px = tid * 4;

        float4 acc4[NL];
        #pragma unroll
        for (int l = 0; l < NL; l++) acc4[l] = make_float4(0.f, 0.f, 0.f, 0.f);

        const float* x3 = l3 + ((size_t)b * C3 + c0) * HW + px;
        __syncthreads();
        #pragma unroll 4
        for (int c = 0; c < 64; c++) {
            float4 xv = *(const float4*)(x3 + (size_t)c * HW);
            float4 wa = *(const float4*)&sWt[c * 12];
            float4 wb = *(const float4*)&sWt[c * 12 + 4];
            float  w8 = sWt[c * 12 + 8];
            float ws[NL] = {wa.x, wa.y, wa.z, wa.w, wb.x, wb.y, wb.z, wb.w, w8};
            #pragma unroll
            for (int l = 0; l < NL; l++) {
                acc4[l].x = fmaf(ws[l], xv.x, acc4[l].x);
                acc4[l].y = fmaf(ws[l], xv.y, acc4[l].y);
                acc4[l].z = fmaf(ws[l], xv.z, acc4[l].z);
                acc4[l].w = fmaf(ws[l], xv.w, acc4[l].w);
            }
        }
        // coalesced float4 stores: [ch][b][l][px]
        float* base = g_part3 + (((size_t)ch3 * B_ + b) * NL) * HW + px;
        #pragma unroll
        for (int l = 0; l < NL; l++)
            *(float4*)(base + (size_t)l * HW) = acc4[l];
    }
}

// ---------------------------------------------------------------------------
// K2: reduce ab4 partials (ab3 reduction is fused into k_softmax)
// ---------------------------------------------------------------------------
__global__ __launch_bounds__(128) void k_red() {
    int idx = blockIdx.x * 128 + threadIdx.x;
    if (idx >= B_ * NL * HW4) return;
    int b = idx / (NL * HW4), r = idx - b * (NL * HW4);
    const float* p = g_p4 + (size_t)b * NCH4 * NL * HW4 + r;
    float s = 0.f;
    #pragma unroll
    for (int ch = 0; ch < NCH4; ch++) s += p[(size_t)ch * NL * HW4];
    g_ab4[idx] = s;
}

// ---------------------------------------------------------------------------
// K3: softmax, parallel over landmarks: block = 9 warps (one per l) x 32 px.
// Each warp-lane: upsample ab4 (4 taps) + 16 coalesced chunk loads; logits
// exchanged via SMEM; per-thread softmax over its pixel's 9 logits.
// ---------------------------------------------------------------------------
__global__ __launch_bounds__(288) void k_softmax(float* __restrict__ out) {
    __shared__ float sL[32][10];
    int lane = threadIdx.x & 31, l = threadIdx.x >> 5;  // l = 0..8
    int g = blockIdx.x * 32 + lane;                     // g < 12544 always
    int b = g / HW, px = g - b * HW;
    int py = px / WW, pxx = px - py * WW;

    float cyf = 0.5f * (float)py - 0.25f;
    int iyf = (int)floorf(cyf);
    float wy = cyf - (float)iyf;
    int iy0 = iyf < 0 ? 0 : iyf;
    int iy1 = (iyf + 1) > 13 ? 13 : (iyf + 1);
    float cxf = 0.5f * (float)pxx - 0.25f;
    int ixf = (int)floorf(cxf);
    float wx = cxf - (float)ixf;
    int ix0 = ixf < 0 ? 0 : ixf;
    int ix1 = (ixf + 1) > 13 ? 13 : (ixf + 1);

    const float* r = g_ab4 + ((size_t)b * NL + l) * HW4;
    float a0 = r[iy0 * H4 + ix0], a1 = r[iy0 * H4 + ix1];
    float b0 = r[iy1 * H4 + ix0], b1 = r[iy1 * H4 + ix1];
    float t = fmaf(wx, a1 - a0, a0);
    float u = fmaf(wx, b1 - b0, b0);
    float s = fmaf(wy, u - t, t);

    #pragma unroll
    for (int ch = 0; ch < NCH3; ch++)
        s += g_part3[(((size_t)ch * B_ + b) * NL + l) * HW + px];

    float lg = 2.f * s - g_asq[l];
    sL[lane][l] = lg;
    __syncthreads();

    float m = -1e30f;
    float v[NL];
    #pragma unroll
    for (int j = 0; j < NL; j++) { v[j] = sL[lane][j]; m = fmaxf(m, v[j]); }
    float den = 0.f;
    #pragma unroll
    for (int j = 0; j < NL; j++) den += __expf(v[j] - m);

    out[MAPS_OFF + ((size_t)b * NL + l) * HW + px] = __expf(lg - m) / den;
}

// ---------------------------------------------------------------------------
// K4: adjoint-downsample of maps: md[b][l][q] = sum_px maps[b][l][px]*w(px,q).
// ---------------------------------------------------------------------------
__global__ __launch_bounds__(128) void k_mapsdown(const float* __restrict__ out) {
    int idx = blockIdx.x * 128 + threadIdx.x;
    if (idx >= B_ * NL * HW4) return;
    int b = idx / (NL * HW4), r = idx - b * (NL * HW4);
    int l = r / HW4, q = r - l * HW4;
    int iy = q / H4, ix = q - iy * H4;

    const float* mp = out + MAPS_OFF + ((size_t)b * NL + l) * HW;

    float s = 0.f;
    #pragma unroll
    for (int dy = 0; dy < 4; dy++) {
        int py = 2 * iy - 1 + dy;
        if (py < 0 || py > 27) continue;
        float cy = 0.5f * (float)py - 0.25f;
        int iyf = (int)floorf(cy);
        float wy = cy - (float)iyf;
        int r0 = iyf < 0 ? 0 : iyf;
        int r1 = (iyf + 1) > 13 ? 13 : (iyf + 1);
        float wr = (r0 == iy ? 1.f - wy : 0.f) + (r1 == iy ? wy : 0.f);
        if (wr == 0.f) continue;
        #pragma unroll
        for (int dx = 0; dx < 4; dx++) {
            int pxx = 2 * ix - 1 + dx;
            if (pxx < 0 || pxx > 27) continue;
            float cx = 0.5f * (float)pxx - 0.25f;
            int ixf = (int)floorf(cx);
            float wxv = cx - (float)ixf;
            int c0 = ixf < 0 ? 0 : ixf;
            int c1 = (ixf + 1) > 13 ? 13 : (ixf + 1);
            float wc = (c0 == ix ? 1.f - wxv : 0.f) + (c1 == ix ? wxv : 0.f);
            if (wc == 0.f) continue;
            s = fmaf(wr * wc, mp[py * WW + pxx], s);
        }
    }
    g_md[idx] = s;
}

// ---------------------------------------------------------------------------
// K5: all_features (+fused modulation average).
// Thread = TWO channels (t and t+128), all 9 landmark accumulators each.
//   x streamed directly from global (two independent contiguous rows),
//   maps/md broadcast from SMEM (uniform address per warp -> conflict-free).
//  cg < 8  : l4 channels (256/block), K=196 against g_md (adjoint trick)
//  cg >= 8 : l3 channels (256/block), K=784 against maps
// ---------------------------------------------------------------------------
__global__ __launch_bounds__(128) void k_feat(const float* __restrict__ l3,
                                              const float* __restrict__ l4,
                                              const float* __restrict__ mod,
                                              float* __restrict__ out) {
    __shared__ float4 sM[NL * 196];   // up to 9 x 784 floats (28.2 KB)

    int b = blockIdx.y, cg = blockIdx.x, tid = threadIdx.x;

    float acc0[NL], acc1[NL];
    #pragma unroll
    for (int l = 0; l < NL; l++) { acc0[l] = 0.f; acc1[l] = 0.f; }

    int cglobal;   // first channel; second is cglobal + 128

    if (cg < 8) {
        int c = cg * 256 + tid;
        cglobal = c;
        const float4* md4 = (const float4*)(g_md + (size_t)b * NL * HW4);
        for (int i = tid; i < NL * 49; i += 128) sM[i] = md4[i];
        __syncthreads();

        const float4* xr0 = (const float4*)(l4 + ((size_t)b * C4 + c) * HW4);
        const float4* xr1 = (const float4*)(l4 + ((size_t)b * C4 + c + 128) * HW4);
        #pragma unroll 7
        for (int i = 0; i < 49; i++) {
            float4 x0 = xr0[i], x1 = xr1[i];
            #pragma unroll
            for (int l = 0; l < NL; l++) {
                float4 m = sM[l * 49 + i];
                acc0[l] = fmaf(x0.x, m.x, acc0[l]);
                acc0[l] = fmaf(x0.y, m.y, acc0[l]);
                acc0[l] = fmaf(x0.z, m.z, acc0[l]);
                acc0[l] = fmaf(x0.w, m.w, acc0[l]);
                acc1[l] = fmaf(x1.x, m.x, acc1[l]);
                acc1[l] = fmaf(x1.y, m.y, acc1[l]);
                acc1[l] = fmaf(x1.z, m.z, acc1[l]);
                acc1[l] = fmaf(x1.w, m.w, acc1[l]);
            }
        }
    } else {
        int c = (cg - 8) * 256 + tid;   // within l3
        cglobal = C4 + c;
        const float4* mp4 = (const float4*)(out + MAPS_OFF + (size_t)b * NL * HW);
        for (int i = tid; i < NL * 196; i += 128) sM[i] = mp4[i];
        __syncthreads();

        const float4* xr0 = (const float4*)(l3 + ((size_t)b * C3 + c) * HW);
        const float4* xr1 = (const float4*)(l3 + ((size_t)b * C3 + c + 128) * HW);
        #pragma unroll 4
        for (int i = 0; i < 196; i++) {
            float4 x0 = xr0[i], x1 = xr1[i];
            #pragma unroll
            for (int l = 0; l < NL; l++) {
                float4 m = sM[l * 196 + i];
                acc0[l] = fmaf(x0.x, m.x, acc0[l]);
                acc0[l] = fmaf(x0.y, m.y, acc0[l]);
                acc0[l] = fmaf(x0.z, m.z, acc0[l]);
                acc0[l] = fmaf(x0.w, m.w, acc0[l]);
                acc1[l] = fmaf(x1.x, m.x, acc1[l]);
                acc1[l] = fmaf(x1.y, m.y, acc1[l]);
                acc1[l] = fmaf(x1.z, m.z, acc1[l]);
                acc1[l] = fmaf(x1.w, m.w, acc1[l]);
            }
        }
    }

    const float sc = 1.0f / (float)HW;
    float* fo0 = out + FEAT_OFF + ((size_t)b * C_ALL + cglobal) * NL;
    float* fo1 = fo0 + 128 * NL;
    float mv0 = 0.f, mv1 = 0.f;
    #pragma unroll
    for (int l = 0; l < NL; l++) {
        float r0 = acc0[l] * sc, r1 = acc1[l] * sc;
        fo0[l] = r0;
        fo1[l] = r1;
        if (l < 8) {
            mv0 = fmaf(r0, mod[cglobal * NL + l], mv0);
            mv1 = fmaf(r1, mod[(cglobal + 128) * NL + l], mv1);
        }
    }
    g_modavg[(size_t)cglobal * B_ + b]         = mv0 * 0.125f;
    g_modavg[(size_t)(cglobal + 128) * B_ + b] = mv1 * 0.125f;
}

// ---------------------------------------------------------------------------
// K6: class_scores[b,k] = sum_c W_class[k,c] * mod_avg[c][b]
// ---------------------------------------------------------------------------
__global__ __launch_bounds__(256) void k_cls(const float* __restrict__ Wc,
                                             float* __restrict__ out) {
    int k = blockIdx.x, tid = threadIdx.x, warp = tid >> 5, lane = tid & 31;
    const float4* wr4 = (const float4*)(Wc + (size_t)k * C_ALL);

    float acc[B_];
    #pragma unroll
    for (int b = 0; b < B_; b++) acc[b] = 0.f;

    for (int c4 = tid; c4 < C_ALL / 4; c4 += 256) {
        float4 wv = wr4[c4];
        float ws[4] = {wv.x, wv.y, wv.z, wv.w};
        #pragma unroll
        for (int j = 0; j < 4; j++) {
            float w = ws[j];
            const float4* mv = (const float4*)(g_modavg + (size_t)(c4 * 4 + j) * B_);
            #pragma unroll
            for (int q = 0; q < 4; q++) {
                float4 m = mv[q];
                acc[4 * q + 0] = fmaf(w, m.x, acc[4 * q + 0]);
                acc[4 * q + 1] = fmaf(w, m.y, acc[4 * q + 1]);
                acc[4 * q + 2] = fmaf(w, m.z, acc[4 * q + 2]);
                acc[4 * q + 3] = fmaf(w, m.w, acc[4 * q + 3]);
            }
        }
    }

    __shared__ float red[8][B_];
    #pragma unroll
    for (int b = 0; b < B_; b++) {
        float v = acc[b];
        #pragma unroll
        for (int o = 16; o; o >>= 1) v += __shfl_xor_sync(0xffffffffu, v, o);
        acc[b] = v;
    }
    if (lane == 0)
        #pragma unroll
        for (int b = 0; b < B_; b++) red[warp][b] = acc[b];
    __syncthreads();
    if (tid < B_) {
        float s = 0.f;
        #pragma unroll
        for (int w = 0; w < 8; w++) s += red[w][tid];
        out[(size_t)tid * NK + k] = s;
    }
}

// ---------------------------------------------------------------------------
extern "C" void kernel_launch(void* const* d_in, const int* in_sizes, int n_in,
                              void* d_out, int out_size) {
    const float* l3  = (const float*)d_in[0];
    const float* l4  = (const float*)d_in[1];
    const float* Wl  = (const float*)d_in[2];
    const float* Wc  = (const float*)d_in[3];
    const float* mod = (const float*)d_in[4];
    float* out = (float*)d_out;

    k_ab<<<dim3(NCHT + 1, B_), 196>>>(l3, l4, Wl);
    k_red<<<(B_ * NL * HW4 + 127) / 128, 128>>>();
    k_softmax<<<(B_ * HW) / 32, 288>>>(out);
    k_mapsdown<<<(B_ * NL * HW4 + 127) / 128, 128>>>(out);
    k_feat<<<dim3(12, B_), 128>>>(l3, l4, mod, out);
    k_cls<<<NK, 256>>>(Wc, out);
}

// round 10
// speedup vs baseline: 1.0579x; 1.0579x over previous
#include <cuda_runtime.h>
#include <math.h>

// Problem constants
#define B_     16
#define HH     28
#define WW     28
#define HW     784
#define C_ALL  3072
#define C4     2048
#define C3     1024
#define H4     14
#define HW4    196
#define NL     9
#define NK     2000

#define NCH4   32   // l4 chunks (64 ch each) over 2048, contraction at 14x14
#define NCH3   16   // l3 chunks (64 ch each) over 1024, contraction at 28x28

// Output layout: class_scores (16*2000), maps (16*9*784), all_features (16*3072*9)
#define CLS_OFF  0
#define MAPS_OFF (B_*NK)                  // 32000
#define FEAT_OFF (MAPS_OFF + B_*NL*HW)    // 144896

// Scratch (static __device__ arrays: allocation-free)
__device__ float g_asq[NL];
__device__ float g_p4[(size_t)B_*NCH4*NL*HW4];        // 3.6 MB partial ab4 [b][ch][l][q]
__device__ float g_part3[(size_t)NCH3*B_*NL*HW];      // 7.1 MB partial ab3 [ch][b][l][px]
__device__ float g_ab4[(size_t)B_*NL*HW4];            // summed ab4 (14x14)
__device__ float g_md[(size_t)B_*NL*HW4];             // adjoint-downsampled maps
__device__ float g_modavg[(size_t)C_ALL*B_];          // [c][b]

// ---------------------------------------------------------------------------
// K0: a_sq[l] = ||W_land[l]||^2  (one block per landmark)
// ---------------------------------------------------------------------------
__global__ void k_asq(const float* __restrict__ Wl) {
    int l = blockIdx.x, tid = threadIdx.x, warp = tid >> 5, lane = tid & 31;
    __shared__ float red[8];
    float s = 0.f;
    for (int i = tid; i < C_ALL; i += 256) {
        float w = Wl[l * C_ALL + i];
        s = fmaf(w, w, s);
    }
    #pragma unroll
    for (int o = 16; o; o >>= 1) s += __shfl_xor_sync(0xffffffffu, s, o);
    if (lane == 0) red[warp] = s;
    __syncthreads();
    if (tid == 0) {
        float t = 0.f;
        #pragma unroll
        for (int w = 0; w < 8; w++) t += red[w];
        g_asq[l] = t;
    }
}

// ---------------------------------------------------------------------------
// K1: fused landmark-logit contraction over 64-channel chunks (768 blocks).
//  chunk <  NCH4 : ab4 partials at 14x14 (direct coalesced LDG, no staging)
//  chunk >= NCH4 : ab3 partials at 28x28 (float4 per thread)
// Weights staged transposed [c][12] -> 2xLDS.128 + LDS per channel.
// ---------------------------------------------------------------------------
__global__ __launch_bounds__(196) void k_ab(const float* __restrict__ l3,
                                            const float* __restrict__ l4,
                                            const float* __restrict__ Wl) {
    __shared__ float sWt[64 * 12];      // 3 KB, [c][l] padded to 12

    int b = blockIdx.y, chunk = blockIdx.x, tid = threadIdx.x;

    if (chunk < NCH4) {
        int c0 = chunk * 64;
        for (int i = tid; i < 64 * NL; i += 196) {
            int c = i / 9, l = i - c * 9;
            sWt[c * 12 + l] = Wl[l * C_ALL + c0 + c];
        }
        const float* l4b = l4 + ((size_t)b * C4 + c0) * HW4 + tid;

        float acc[NL];
        #pragma unroll
        for (int l = 0; l < NL; l++) acc[l] = 0.f;

        __syncthreads();
        #pragma unroll 8
        for (int c = 0; c < 64; c++) {
            float x = l4b[(size_t)c * HW4];        // coalesced LDG.32
            float4 wa = *(const float4*)&sWt[c * 12];
            float4 wb = *(const float4*)&sWt[c * 12 + 4];
            float  w8 = sWt[c * 12 + 8];
            acc[0] = fmaf(wa.x, x, acc[0]);
            acc[1] = fmaf(wa.y, x, acc[1]);
            acc[2] = fmaf(wa.z, x, acc[2]);
            acc[3] = fmaf(wa.w, x, acc[3]);
            acc[4] = fmaf(wb.x, x, acc[4]);
            acc[5] = fmaf(wb.y, x, acc[5]);
            acc[6] = fmaf(wb.z, x, acc[6]);
            acc[7] = fmaf(wb.w, x, acc[7]);
            acc[8] = fmaf(w8,   x, acc[8]);
        }
        float* dst = g_p4 + ((size_t)(b * NCH4 + chunk) * NL) * HW4 + tid;
        #pragma unroll
        for (int l = 0; l < NL; l++) dst[(size_t)l * HW4] = acc[l];
    } else {
        int ch3 = chunk - NCH4;
        int c0 = ch3 * 64;
        for (int i = tid; i < 64 * NL; i += 196) {
            int c = i / 9, l = i - c * 9;
            sWt[c * 12 + l] = Wl[l * C_ALL + C4 + c0 + c];
        }
        int px = tid * 4;

        float4 acc4[NL];
        #pragma unroll
        for (int l = 0; l < NL; l++) acc4[l] = make_float4(0.f, 0.f, 0.f, 0.f);

        const float* x3 = l3 + ((size_t)b * C3 + c0) * HW + px;
        __syncthreads();
        #pragma unroll 4
        for (int c = 0; c < 64; c++) {
            float4 xv = *(const float4*)(x3 + (size_t)c * HW);
            float4 wa = *(const float4*)&sWt[c * 12];
            float4 wb = *(const float4*)&sWt[c * 12 + 4];
            float  w8 = sWt[c * 12 + 8];
            float ws[NL] = {wa.x, wa.y, wa.z, wa.w, wb.x, wb.y, wb.z, wb.w, w8};
            #pragma unroll
            for (int l = 0; l < NL; l++) {
                acc4[l].x = fmaf(ws[l], xv.x, acc4[l].x);
                acc4[l].y = fmaf(ws[l], xv.y, acc4[l].y);
                acc4[l].z = fmaf(ws[l], xv.z, acc4[l].z);
                acc4[l].w = fmaf(ws[l], xv.w, acc4[l].w);
            }
        }
        // coalesced float4 stores: [ch][b][l][px]
        float* base = g_part3 + (((size_t)ch3 * B_ + b) * NL) * HW + px;
        #pragma unroll
        for (int l = 0; l < NL; l++)
            *(float4*)(base + (size_t)l * HW) = acc4[l];
    }
}

// ---------------------------------------------------------------------------
// K2: reduce ab4 partials (ab3 reduction is fused into k_softmax)
// ---------------------------------------------------------------------------
__global__ void k_red() {
    int idx = blockIdx.x * 64 + threadIdx.x;
    if (idx >= B_ * NL * HW4) return;
    int b = idx / (NL * HW4), r = idx - b * (NL * HW4);
    const float* p = g_p4 + (size_t)b * NCH4 * NL * HW4 + r;
    float s = 0.f;
    #pragma unroll
    for (int ch = 0; ch < NCH4; ch++) s += p[(size_t)ch * NL * HW4];
    g_ab4[idx] = s;
}

// ---------------------------------------------------------------------------
// K3: softmax, parallel over landmarks: block = 9 warps (one per l) x 32 px.
// Each warp-lane: upsample ab4 (4 taps) + 16 coalesced chunk loads; logits
// exchanged via SMEM; per-thread softmax over its pixel's 9 logits.
// ---------------------------------------------------------------------------
__global__ __launch_bounds__(288) void k_softmax(float* __restrict__ out) {
    __shared__ float sL[32][10];
    int lane = threadIdx.x & 31, l = threadIdx.x >> 5;  // l = 0..8
    int g = blockIdx.x * 32 + lane;                     // g < 12544 always
    int b = g / HW, px = g - b * HW;
    int py = px / WW, pxx = px - py * WW;

    float cyf = 0.5f * (float)py - 0.25f;
    int iyf = (int)floorf(cyf);
    float wy = cyf - (float)iyf;
    int iy0 = iyf < 0 ? 0 : iyf;
    int iy1 = (iyf + 1) > 13 ? 13 : (iyf + 1);
    float cxf = 0.5f * (float)pxx - 0.25f;
    int ixf = (int)floorf(cxf);
    float wx = cxf - (float)ixf;
    int ix0 = ixf < 0 ? 0 : ixf;
    int ix1 = (ixf + 1) > 13 ? 13 : (ixf + 1);

    const float* r = g_ab4 + ((size_t)b * NL + l) * HW4;
    float a0 = r[iy0 * H4 + ix0], a1 = r[iy0 * H4 + ix1];
    float b0 = r[iy1 * H4 + ix0], b1 = r[iy1 * H4 + ix1];
    float t = fmaf(wx, a1 - a0, a0);
    float u = fmaf(wx, b1 - b0, b0);
    float s = fmaf(wy, u - t, t);

    #pragma unroll
    for (int ch = 0; ch < NCH3; ch++)
        s += g_part3[(((size_t)ch * B_ + b) * NL + l) * HW + px];

    float lg = 2.f * s - g_asq[l];
    sL[lane][l] = lg;
    __syncthreads();

    float m = -1e30f;
    float v[NL];
    #pragma unroll
    for (int j = 0; j < NL; j++) { v[j] = sL[lane][j]; m = fmaxf(m, v[j]); }
    float den = 0.f;
    #pragma unroll
    for (int j = 0; j < NL; j++) den += __expf(v[j] - m);

    out[MAPS_OFF + ((size_t)b * NL + l) * HW + px] = __expf(lg - m) / den;
}

// ---------------------------------------------------------------------------
// K4: adjoint-downsample of maps: md[b][l][q] = sum_px maps[b][l][px]*w(px,q).
// ---------------------------------------------------------------------------
__global__ __launch_bounds__(64) void k_mapsdown(const float* __restrict__ out) {
    int idx = blockIdx.x * 64 + threadIdx.x;
    if (idx >= B_ * NL * HW4) return;
    int b = idx / (NL * HW4), r = idx - b * (NL * HW4);
    int l = r / HW4, q = r - l * HW4;
    int iy = q / H4, ix = q - iy * H4;

    const float* mp = out + MAPS_OFF + ((size_t)b * NL + l) * HW;

    float s = 0.f;
    #pragma unroll
    for (int dy = 0; dy < 4; dy++) {
        int py = 2 * iy - 1 + dy;
        if (py < 0 || py > 27) continue;
        float cy = 0.5f * (float)py - 0.25f;
        int iyf = (int)floorf(cy);
        float wy = cy - (float)iyf;
        int r0 = iyf < 0 ? 0 : iyf;
        int r1 = (iyf + 1) > 13 ? 13 : (iyf + 1);
        float wr = (r0 == iy ? 1.f - wy : 0.f) + (r1 == iy ? wy : 0.f);
        if (wr == 0.f) continue;
        #pragma unroll
        for (int dx = 0; dx < 4; dx++) {
            int pxx = 2 * ix - 1 + dx;
            if (pxx < 0 || pxx > 27) continue;
            float cx = 0.5f * (float)pxx - 0.25f;
            int ixf = (int)floorf(cx);
            float wxv = cx - (float)ixf;
            int c0 = ixf < 0 ? 0 : ixf;
            int c1 = (ixf + 1) > 13 ? 13 : (ixf + 1);
            float wc = (c0 == ix ? 1.f - wxv : 0.f) + (c1 == ix ? wxv : 0.f);
            if (wc == 0.f) continue;
            s = fmaf(wr * wc, mp[py * WW + pxx], s);
        }
    }
    g_md[idx] = s;
}

// ---------------------------------------------------------------------------
// K5: all_features (+fused modulation average).
// Thread = one channel, owns all 9 landmark accumulators.
//   x streamed directly from global (own contiguous row, L1-friendly),
//   maps/md broadcast from SMEM (uniform address per warp -> conflict-free).
//  cg <  16 : l4 channels (128/block), K=196 against g_md (adjoint trick)
//  cg >= 16 : l3 channels (128/block), K=784 against maps
// No barriers in hot loop, no reductions, modavg computed in registers.
// ---------------------------------------------------------------------------
__global__ __launch_bounds__(128) void k_feat(const float* __restrict__ l3,
                                              const float* __restrict__ l4,
                                              const float* __restrict__ mod,
                                              float* __restrict__ out) {
    __shared__ float4 sM[NL * 196];   // up to 9 x 784 floats (28.2 KB)

    int b = blockIdx.y, cg = blockIdx.x, tid = threadIdx.x;

    float acc[NL];
    #pragma unroll
    for (int l = 0; l < NL; l++) acc[l] = 0.f;

    int cglobal;

    if (cg < 16) {
        int c = cg * 128 + tid;
        cglobal = c;
        const float4* md4 = (const float4*)(g_md + (size_t)b * NL * HW4);
        for (int i = tid; i < NL * 49; i += 128) sM[i] = md4[i];
        __syncthreads();

        const float4* xr = (const float4*)(l4 + ((size_t)b * C4 + c) * HW4);
        #pragma unroll 7
        for (int i = 0; i < 49; i++) {
            float4 x = xr[i];
            #pragma unroll
            for (int l = 0; l < NL; l++) {
                float4 m = sM[l * 49 + i];
                acc[l] = fmaf(x.x, m.x, acc[l]);
                acc[l] = fmaf(x.y, m.y, acc[l]);
                acc[l] = fmaf(x.z, m.z, acc[l]);
                acc[l] = fmaf(x.w, m.w, acc[l]);
            }
        }
    } else {
        int c = (cg - 16) * 128 + tid;   // within l3
        cglobal = C4 + c;
        const float4* mp4 = (const float4*)(out + MAPS_OFF + (size_t)b * NL * HW);
        for (int i = tid; i < NL * 196; i += 128) sM[i] = mp4[i];
        __syncthreads();

        const float4* xr = (const float4*)(l3 + ((size_t)b * C3 + c) * HW);
        #pragma unroll 4
        for (int i = 0; i < 196; i++) {
            float4 x = xr[i];
            #pragma unroll
            for (int l = 0; l < NL; l++) {
                float4 m = sM[l * 196 + i];
                acc[l] = fmaf(x.x, m.x, acc[l]);
                acc[l] = fmaf(x.y, m.y, acc[l]);
                acc[l] = fmaf(x.z, m.z, acc[l]);
                acc[l] = fmaf(x.w, m.w, acc[l]);
            }
        }
    }

    const float sc = 1.0f / (float)HW;
    float* fo = out + FEAT_OFF + ((size_t)b * C_ALL + cglobal) * NL;
    float mv = 0.f;
    #pragma unroll
    for (int l = 0; l < NL; l++) {
        float r = acc[l] * sc;
        fo[l] = r;
        if (l < 8) mv = fmaf(r, mod[cglobal * NL + l], mv);
    }
    g_modavg[(size_t)cglobal * B_ + b] = mv * 0.125f;
}

// ---------------------------------------------------------------------------
// K6: class_scores[b,k] = sum_c W_class[k,c] * mod_avg[c][b]
// float4 weight reads for 4x MLP on the W_class stream.
// ---------------------------------------------------------------------------
__global__ __launch_bounds__(256) void k_cls(const float* __restrict__ Wc,
                                             float* __restrict__ out) {
    int k = blockIdx.x, tid = threadIdx.x, warp = tid >> 5, lane = tid & 31;
    const float4* wr4 = (const float4*)(Wc + (size_t)k * C_ALL);

    float acc[B_];
    #pragma unroll
    for (int b = 0; b < B_; b++) acc[b] = 0.f;

    for (int c4 = tid; c4 < C_ALL / 4; c4 += 256) {
        float4 wv = wr4[c4];
        float ws[4] = {wv.x, wv.y, wv.z, wv.w};
        #pragma unroll
        for (int j = 0; j < 4; j++) {
            float w = ws[j];
            const float4* mv = (const float4*)(g_modavg + (size_t)(c4 * 4 + j) * B_);
            #pragma unroll
            for (int q = 0; q < 4; q++) {
                float4 m = mv[q];
                acc[4 * q + 0] = fmaf(w, m.x, acc[4 * q + 0]);
                acc[4 * q + 1] = fmaf(w, m.y, acc[4 * q + 1]);
                acc[4 * q + 2] = fmaf(w, m.z, acc[4 * q + 2]);
                acc[4 * q + 3] = fmaf(w, m.w, acc[4 * q + 3]);
            }
        }
    }

    __shared__ float red[8][B_];
    #pragma unroll
    for (int b = 0; b < B_; b++) {
        float v = acc[b];
        #pragma unroll
        for (int o = 16; o; o >>= 1) v += __shfl_xor_sync(0xffffffffu, v, o);
        acc[b] = v;
    }
    if (lane == 0)
        #pragma unroll
        for (int b = 0; b < B_; b++) red[warp][b] = acc[b];
    __syncthreads();
    if (tid < B_) {
        float s = 0.f;
        #pragma unroll
        for (int w = 0; w < 8; w++) s += red[w][tid];
        out[(size_t)tid * NK + k] = s;
    }
}

// ---------------------------------------------------------------------------
extern "C" void kernel_launch(void* const* d_in, const int* in_sizes, int n_in,
                              void* d_out, int out_size) {
    const float* l3  = (const float*)d_in[0];
    const float* l4  = (const float*)d_in[1];
    const float* Wl  = (const float*)d_in[2];
    const float* Wc  = (const float*)d_in[3];
    const float* mod = (const float*)d_in[4];
    float* out = (float*)d_out;

    k_asq<<<NL, 256>>>(Wl);
    k_ab<<<dim3(NCH4 + NCH3, B_), 196>>>(l3, l4, Wl);
    k_red<<<(B_ * NL * HW4 + 63) / 64, 64>>>();
    k_softmax<<<(B_ * HW) / 32, 288>>>(out);
    k_mapsdown<<<(B_ * NL * HW4 + 63) / 64, 64>>>(out);
    k_feat<<<dim3(24, B_), 128>>>(l3, l4, mod, out);
    k_cls<<<NK, 256>>>(Wc, out);
}

// round 11
// speedup vs baseline: 1.3455x; 1.2719x over previous
#include <cuda_runtime.h>
#include <math.h>

// Problem constants
#define B_     16
#define HH     28
#define WW     28
#define HW     784
#define C_ALL  3072
#define C4     2048
#define C3     1024
#define H4     14
#define HW4    196
#define NL     9
#define NK     2000

#define NCH4   32   // l4 chunks (64 ch each) over 2048, contraction at 14x14
#define NCH3   16   // l3 chunks (64 ch each) over 1024, contraction at 28x28

// Output layout: class_scores (16*2000), maps (16*9*784), all_features (16*3072*9)
#define CLS_OFF  0
#define MAPS_OFF (B_*NK)                  // 32000
#define FEAT_OFF (MAPS_OFF + B_*NL*HW)    // 144896

// Scratch (static __device__ arrays: allocation-free)
__device__ float g_asq[NL];
__device__ float g_p4[(size_t)B_*NCH4*NL*HW4];        // 3.6 MB partial ab4 [b][ch][l][q]
__device__ float g_part3[(size_t)NCH3*B_*NL*HW];      // 7.1 MB partial ab3 [ch][b][l][px]
__device__ float g_ab4[(size_t)B_*NL*HW4];            // summed ab4 (14x14)
__device__ float g_md[(size_t)B_*NL*HW4];             // adjoint-downsampled maps
__device__ float g_modavg[(size_t)C_ALL*B_];          // [c][b]

// ---------------------------------------------------------------------------
// K0: a_sq[l] = ||W_land[l]||^2  (one block per landmark)
// ---------------------------------------------------------------------------
__global__ void k_asq(const float* __restrict__ Wl) {
    int l = blockIdx.x, tid = threadIdx.x, warp = tid >> 5, lane = tid & 31;
    __shared__ float red[8];
    float s = 0.f;
    for (int i = tid; i < C_ALL; i += 256) {
        float w = Wl[l * C_ALL + i];
        s = fmaf(w, w, s);
    }
    #pragma unroll
    for (int o = 16; o; o >>= 1) s += __shfl_xor_sync(0xffffffffu, s, o);
    if (lane == 0) red[warp] = s;
    __syncthreads();
    if (tid == 0) {
        float t = 0.f;
        #pragma unroll
        for (int w = 0; w < 8; w++) t += red[w];
        g_asq[l] = t;
    }
}

// ---------------------------------------------------------------------------
// K1: fused landmark-logit contraction over 64-channel chunks (768 blocks).
//  chunk <  NCH4 : ab4 partials at 14x14 (direct coalesced LDG, no staging)
//  chunk >= NCH4 : ab3 partials at 28x28 (float4 per thread)
// Weights staged transposed [c][12] -> 2xLDS.128 + LDS per channel.
// ---------------------------------------------------------------------------
__global__ __launch_bounds__(196) void k_ab(const float* __restrict__ l3,
                                            const float* __restrict__ l4,
                                            const float* __restrict__ Wl) {
    __shared__ float sWt[64 * 12];      // 3 KB, [c][l] padded to 12

    int b = blockIdx.y, chunk = blockIdx.x, tid = threadIdx.x;

    if (chunk < NCH4) {
        int c0 = chunk * 64;
        for (int i = tid; i < 64 * NL; i += 196) {
            int c = i / 9, l = i - c * 9;
            sWt[c * 12 + l] = Wl[l * C_ALL + c0 + c];
        }
        const float* l4b = l4 + ((size_t)b * C4 + c0) * HW4 + tid;

        float acc[NL];
        #pragma unroll
        for (int l = 0; l < NL; l++) acc[l] = 0.f;

        __syncthreads();
        #pragma unroll 8
        for (int c = 0; c < 64; c++) {
            float x = l4b[(size_t)c * HW4];        // coalesced LDG.32
            float4 wa = *(const float4*)&sWt[c * 12];
            float4 wb = *(const float4*)&sWt[c * 12 + 4];
            float  w8 = sWt[c * 12 + 8];
            acc[0] = fmaf(wa.x, x, acc[0]);
            acc[1] = fmaf(wa.y, x, acc[1]);
            acc[2] = fmaf(wa.z, x, acc[2]);
            acc[3] = fmaf(wa.w, x, acc[3]);
            acc[4] = fmaf(wb.x, x, acc[4]);
            acc[5] = fmaf(wb.y, x, acc[5]);
            acc[6] = fmaf(wb.z, x, acc[6]);
            acc[7] = fmaf(wb.w, x, acc[7]);
            acc[8] = fmaf(w8,   x, acc[8]);
        }
        float* dst = g_p4 + ((size_t)(b * NCH4 + chunk) * NL) * HW4 + tid;
        #pragma unroll
        for (int l = 0; l < NL; l++) dst[(size_t)l * HW4] = acc[l];
    } else {
        int ch3 = chunk - NCH4;
        int c0 = ch3 * 64;
        for (int i = tid; i < 64 * NL; i += 196) {
            int c = i / 9, l = i - c * 9;
            sWt[c * 12 + l] = Wl[l * C_ALL + C4 + c0 + c];
        }
        int px = tid * 4;

        float4 acc4[NL];
        #pragma unroll
        for (int l = 0; l < NL; l++) acc4[l] = make_float4(0.f, 0.f, 0.f, 0.f);

        const float* x3 = l3 + ((size_t)b * C3 + c0) * HW + px;
        __syncthreads();
        #pragma unroll 4
        for (int c = 0; c < 64; c++) {
            float4 xv = *(const float4*)(x3 + (size_t)c * HW);
            float4 wa = *(const float4*)&sWt[c * 12];
            float4 wb = *(const float4*)&sWt[c * 12 + 4];
            float  w8 = sWt[c * 12 + 8];
            float ws[NL] = {wa.x, wa.y, wa.z, wa.w, wb.x, wb.y, wb.z, wb.w, w8};
            #pragma unroll
            for (int l = 0; l < NL; l++) {
                acc4[l].x = fmaf(ws[l], xv.x, acc4[l].x);
                acc4[l].y = fmaf(ws[l], xv.y, acc4[l].y);
                acc4[l].z = fmaf(ws[l], xv.z, acc4[l].z);
                acc4[l].w = fmaf(ws[l], xv.w, acc4[l].w);
            }
        }
        // coalesced float4 stores: [ch][b][l][px]
        float* base = g_part3 + (((size_t)ch3 * B_ + b) * NL) * HW + px;
        #pragma unroll
        for (int l = 0; l < NL; l++)
            *(float4*)(base + (size_t)l * HW) = acc4[l];
    }
}

// ---------------------------------------------------------------------------
// K2: reduce ab4 partials (ab3 reduction is fused into k_softmax)
// ---------------------------------------------------------------------------
__global__ void k_red() {
    int idx = blockIdx.x * 64 + threadIdx.x;
    if (idx >= B_ * NL * HW4) return;
    int b = idx / (NL * HW4), r = idx - b * (NL * HW4);
    const float* p = g_p4 + (size_t)b * NCH4 * NL * HW4 + r;
    float s = 0.f;
    #pragma unroll
    for (int ch = 0; ch < NCH4; ch++) s += p[(size_t)ch * NL * HW4];
    g_ab4[idx] = s;
}

// ---------------------------------------------------------------------------
// K3: softmax, parallel over landmarks: block = 9 warps (one per l) x 32 px.
// Each warp-lane: upsample ab4 (4 taps) + 16 coalesced chunk loads; logits
// exchanged via SMEM; per-thread softmax over its pixel's 9 logits.
// ---------------------------------------------------------------------------
__global__ __launch_bounds__(288) void k_softmax(float* __restrict__ out) {
    __shared__ float sL[32][10];
    int lane = threadIdx.x & 31, l = threadIdx.x >> 5;  // l = 0..8
    int g = blockIdx.x * 32 + lane;                     // g < 12544 always
    int b = g / HW, px = g - b * HW;
    int py = px / WW, pxx = px - py * WW;

    float cyf = 0.5f * (float)py - 0.25f;
    int iyf = (int)floorf(cyf);
    float wy = cyf - (float)iyf;
    int iy0 = iyf < 0 ? 0 : iyf;
    int iy1 = (iyf + 1) > 13 ? 13 : (iyf + 1);
    float cxf = 0.5f * (float)pxx - 0.25f;
    int ixf = (int)floorf(cxf);
    float wx = cxf - (float)ixf;
    int ix0 = ixf < 0 ? 0 : ixf;
    int ix1 = (ixf + 1) > 13 ? 13 : (ixf + 1);

    const float* r = g_ab4 + ((size_t)b * NL + l) * HW4;
    float a0 = r[iy0 * H4 + ix0], a1 = r[iy0 * H4 + ix1];
    float b0 = r[iy1 * H4 + ix0], b1 = r[iy1 * H4 + ix1];
    float t = fmaf(wx, a1 - a0, a0);
    float u = fmaf(wx, b1 - b0, b0);
    float s = fmaf(wy, u - t, t);

    #pragma unroll
    for (int ch = 0; ch < NCH3; ch++)
        s += g_part3[(((size_t)ch * B_ + b) * NL + l) * HW + px];

    float lg = 2.f * s - g_asq[l];
    sL[lane][l] = lg;
    __syncthreads();

    float m = -1e30f;
    float v[NL];
    #pragma unroll
    for (int j = 0; j < NL; j++) { v[j] = sL[lane][j]; m = fmaxf(m, v[j]); }
    float den = 0.f;
    #pragma unroll
    for (int j = 0; j < NL; j++) den += __expf(v[j] - m);

    out[MAPS_OFF + ((size_t)b * NL + l) * HW + px] = __expf(lg - m) / den;
}

// ---------------------------------------------------------------------------
// K4: adjoint-downsample of maps: md[b][l][q] = sum_px maps[b][l][px]*w(px,q).
// ---------------------------------------------------------------------------
__global__ __launch_bounds__(64) void k_mapsdown(const float* __restrict__ out) {
    int idx = blockIdx.x * 64 + threadIdx.x;
    if (idx >= B_ * NL * HW4) return;
    int b = idx / (NL * HW4), r = idx - b * (NL * HW4);
    int l = r / HW4, q = r - l * HW4;
    int iy = q / H4, ix = q - iy * H4;

    const float* mp = out + MAPS_OFF + ((size_t)b * NL + l) * HW;

    float s = 0.f;
    #pragma unroll
    for (int dy = 0; dy < 4; dy++) {
        int py = 2 * iy - 1 + dy;
        if (py < 0 || py > 27) continue;
        float cy = 0.5f * (float)py - 0.25f;
        int iyf = (int)floorf(cy);
        float wy = cy - (float)iyf;
        int r0 = iyf < 0 ? 0 : iyf;
        int r1 = (iyf + 1) > 13 ? 13 : (iyf + 1);
        float wr = (r0 == iy ? 1.f - wy : 0.f) + (r1 == iy ? wy : 0.f);
        if (wr == 0.f) continue;
        #pragma unroll
        for (int dx = 0; dx < 4; dx++) {
            int pxx = 2 * ix - 1 + dx;
            if (pxx < 0 || pxx > 27) continue;
            float cx = 0.5f * (float)pxx - 0.25f;
            int ixf = (int)floorf(cx);
            float wxv = cx - (float)ixf;
            int c0 = ixf < 0 ? 0 : ixf;
            int c1 = (ixf + 1) > 13 ? 13 : (ixf + 1);
            float wc = (c0 == ix ? 1.f - wxv : 0.f) + (c1 == ix ? wxv : 0.f);
            if (wc == 0.f) continue;
            s = fmaf(wr * wc, mp[py * WW + pxx], s);
        }
    }
    g_md[idx] = s;
}

// ---------------------------------------------------------------------------
// K5: all_features (+fused modulation average).
// Thread = one channel, owns all 9 landmark accumulators.
//   x streamed directly from global (own contiguous row, L1-friendly),
//   maps/md broadcast from SMEM (uniform address per warp -> conflict-free).
//  cg <  16 : l4 channels (128/block), K=196 against g_md (adjoint trick)
//  cg >= 16 : l3 channels (128/block), K=784 against maps
// No barriers in hot loop, no reductions, modavg computed in registers.
// ---------------------------------------------------------------------------
__global__ __launch_bounds__(128) void k_feat(const float* __restrict__ l3,
                                              const float* __restrict__ l4,
                                              const float* __restrict__ mod,
                                              float* __restrict__ out) {
    __shared__ float4 sM[NL * 196];   // up to 9 x 784 floats (28.2 KB)

    int b = blockIdx.y, cg = blockIdx.x, tid = threadIdx.x;

    float acc[NL];
    #pragma unroll
    for (int l = 0; l < NL; l++) acc[l] = 0.f;

    int cglobal;

    if (cg < 16) {
        int c = cg * 128 + tid;
        cglobal = c;
        const float4* md4 = (const float4*)(g_md + (size_t)b * NL * HW4);
        for (int i = tid; i < NL * 49; i += 128) sM[i] = md4[i];
        __syncthreads();

        const float4* xr = (const float4*)(l4 + ((size_t)b * C4 + c) * HW4);
        #pragma unroll 7
        for (int i = 0; i < 49; i++) {
            float4 x = xr[i];
            #pragma unroll
            for (int l = 0; l < NL; l++) {
                float4 m = sM[l * 49 + i];
                acc[l] = fmaf(x.x, m.x, acc[l]);
                acc[l] = fmaf(x.y, m.y, acc[l]);
                acc[l] = fmaf(x.z, m.z, acc[l]);
                acc[l] = fmaf(x.w, m.w, acc[l]);
            }
        }
    } else {
        int c = (cg - 16) * 128 + tid;   // within l3
        cglobal = C4 + c;
        const float4* mp4 = (const float4*)(out + MAPS_OFF + (size_t)b * NL * HW);
        for (int i = tid; i < NL * 196; i += 128) sM[i] = mp4[i];
        __syncthreads();

        const float4* xr = (const float4*)(l3 + ((size_t)b * C3 + c) * HW);
        #pragma unroll 4
        for (int i = 0; i < 196; i++) {
            float4 x = xr[i];
            #pragma unroll
            for (int l = 0; l < NL; l++) {
                float4 m = sM[l * 196 + i];
                acc[l] = fmaf(x.x, m.x, acc[l]);
                acc[l] = fmaf(x.y, m.y, acc[l]);
                acc[l] = fmaf(x.z, m.z, acc[l]);
                acc[l] = fmaf(x.w, m.w, acc[l]);
            }
        }
    }

    const float sc = 1.0f / (float)HW;
    float* fo = out + FEAT_OFF + ((size_t)b * C_ALL + cglobal) * NL;
    float mv = 0.f;
    #pragma unroll
    for (int l = 0; l < NL; l++) {
        float r = acc[l] * sc;
        fo[l] = r;
        if (l < 8) mv = fmaf(r, mod[cglobal * NL + l], mv);
    }
    g_modavg[(size_t)cglobal * B_ + b] = mv * 0.125f;
}

// ---------------------------------------------------------------------------
// K6: class_scores[b,k] = sum_c W_class[k,c] * mod_avg[c][b]
// (scalar weight reads — the R8 version; float4 variant regressed)
// ---------------------------------------------------------------------------
__global__ __launch_bounds__(256) void k_cls(const float* __restrict__ Wc,
                                             float* __restrict__ out) {
    int k = blockIdx.x, tid = threadIdx.x, warp = tid >> 5, lane = tid & 31;
    const float* wr = Wc + (size_t)k * C_ALL;

    float acc[B_];
    #pragma unroll
    for (int b = 0; b < B_; b++) acc[b] = 0.f;

    for (int c = tid; c < C_ALL; c += 256) {
        float w = wr[c];
        const float4* mv = (const float4*)(g_modavg + (size_t)c * B_);
        #pragma unroll
        for (int q = 0; q < 4; q++) {
            float4 m = mv[q];
            acc[4 * q + 0] = fmaf(w, m.x, acc[4 * q + 0]);
            acc[4 * q + 1] = fmaf(w, m.y, acc[4 * q + 1]);
            acc[4 * q + 2] = fmaf(w, m.z, acc[4 * q + 2]);
            acc[4 * q + 3] = fmaf(w, m.w, acc[4 * q + 3]);
        }
    }

    __shared__ float red[8][B_];
    #pragma unroll
    for (int b = 0; b < B_; b++) {
        float v = acc[b];
        #pragma unroll
        for (int o = 16; o; o >>= 1) v += __shfl_xor_sync(0xffffffffu, v, o);
        acc[b] = v;
    }
    if (lane == 0)
        #pragma unroll
        for (int b = 0; b < B_; b++) red[warp][b] = acc[b];
    __syncthreads();
    if (tid < B_) {
        float s = 0.f;
        #pragma unroll
        for (int w = 0; w < 8; w++) s += red[w][tid];
        out[(size_t)tid * NK + k] = s;
    }
}

// ---------------------------------------------------------------------------
extern "C" void kernel_launch(void* const* d_in, const int* in_sizes, int n_in,
                              void* d_out, int out_size) {
    const float* l3  = (const float*)d_in[0];
    const float* l4  = (const float*)d_in[1];
    const float* Wl  = (const float*)d_in[2];
    const float* Wc  = (const float*)d_in[3];
    const float* mod = (const float*)d_in[4];
    float* out = (float*)d_out;

    k_asq<<<NL, 256>>>(Wl);
    k_ab<<<dim3(NCH4 + NCH3, B_), 196>>>(l3, l4, Wl);
    k_red<<<(B_ * NL * HW4 + 63) / 64, 64>>>();
    k_softmax<<<(B_ * HW) / 32, 288>>>(out);
    k_mapsdown<<<(B_ * NL * HW4 + 63) / 64, 64>>>(out);
    k_feat<<<dim3(24, B_), 128>>>(l3, l4, mod, out);
    k_cls<<<NK, 256>>>(Wc, out);
}

// round 12
// speedup vs baseline: 1.3644x; 1.0140x over previous
#include <cuda_runtime.h>
#include <math.h>

// Problem constants
#define B_     16
#define HH     28
#define WW     28
#define HW     784
#define C_ALL  3072
#define C4     2048
#define C3     1024
#define H4     14
#define HW4    196
#define NL     9
#define NK     2000

#define NCH4   32   // l4 chunks (64 ch each) over 2048, contraction at 14x14
#define NCH3   16   // l3 chunks (64 ch each) over 1024, contraction at 28x28

// Output layout
#define CLS_OFF  0
#define MAPS_OFF (B_*NK)                  // 32000
#define FEAT_OFF (MAPS_OFF + B_*NL*HW)    // 144896

typedef unsigned long long ull;

// packed f32x2 helpers (ptxas never emits FFMA2 from C++; PTX required)
__device__ __forceinline__ ull pk2(float lo, float hi) {
    ull r; asm("mov.b64 %0, {%1, %2};" : "=l"(r) : "f"(lo), "f"(hi)); return r;
}
__device__ __forceinline__ void fma2(ull& d, ull a, ull b) {
    asm("fma.rn.f32x2 %0, %1, %2, %0;" : "+l"(d) : "l"(a), "l"(b));
}
__device__ __forceinline__ float2 up2(ull v) {
    float2 f; asm("mov.b64 {%0, %1}, %2;" : "=f"(f.x), "=f"(f.y) : "l"(v)); return f;
}

// Scratch (static __device__ arrays: allocation-free)
__device__ float g_asq[NL];
__device__ float g_p4[(size_t)B_*NCH4*NL*HW4];        // partial ab4 [b][ch][l][q]
__device__ float g_part3[(size_t)NCH3*B_*NL*HW];      // partial ab3 [ch][b][l][px]
__device__ float g_ab4[(size_t)B_*NL*HW4];            // summed ab4 (14x14)
__device__ float g_md[(size_t)B_*NL*HW4];             // adjoint-downsampled maps
__device__ float g_modavg[(size_t)C_ALL*B_];          // [c][b]

// ---------------------------------------------------------------------------
// K0: a_sq[l] = ||W_land[l]||^2  (one block per landmark)
// ---------------------------------------------------------------------------
__global__ void k_asq(const float* __restrict__ Wl) {
    int l = blockIdx.x, tid = threadIdx.x, warp = tid >> 5, lane = tid & 31;
    __shared__ float red[8];
    float s = 0.f;
    for (int i = tid; i < C_ALL; i += 256) {
        float w = Wl[l * C_ALL + i];
        s = fmaf(w, w, s);
    }
    #pragma unroll
    for (int o = 16; o; o >>= 1) s += __shfl_xor_sync(0xffffffffu, s, o);
    if (lane == 0) red[warp] = s;
    __syncthreads();
    if (tid == 0) {
        float t = 0.f;
        #pragma unroll
        for (int w = 0; w < 8; w++) t += red[w];
        g_asq[l] = t;
    }
}

// ---------------------------------------------------------------------------
// K1: fused landmark-logit contraction (64-ch chunks, 768 blocks), FFMA2.
// ---------------------------------------------------------------------------
__global__ __launch_bounds__(196) void k_ab(const float* __restrict__ l3,
                                            const float* __restrict__ l4,
                                            const float* __restrict__ Wl) {
    __shared__ __align__(16) float sWt[64 * 12];   // [c][l] padded to 12

    int b = blockIdx.y, chunk = blockIdx.x, tid = threadIdx.x;

    if (chunk < NCH4) {
        int c0 = chunk * 64;
        for (int i = tid; i < 64 * NL; i += 196) {
            int c = i / 9, l = i - c * 9;
            sWt[c * 12 + l] = Wl[l * C_ALL + c0 + c];
        }
        const float* l4b = l4 + ((size_t)b * C4 + c0) * HW4 + tid;

        ull acc2[4] = {0ull, 0ull, 0ull, 0ull};   // (l0,l1)(l2,l3)(l4,l5)(l6,l7)
        float acc8 = 0.f;

        __syncthreads();
        #pragma unroll 8
        for (int c = 0; c < 64; c++) {
            float x = l4b[(size_t)c * HW4];        // coalesced LDG.32
            ull xx = pk2(x, x);
            const ulonglong2* wp = (const ulonglong2*)&sWt[c * 12];
            ulonglong2 w01 = wp[0];                // (l0,l1),(l2,l3)
            ulonglong2 w23 = wp[1];                // (l4,l5),(l6,l7)
            float w8 = sWt[c * 12 + 8];
            fma2(acc2[0], xx, w01.x);
            fma2(acc2[1], xx, w01.y);
            fma2(acc2[2], xx, w23.x);
            fma2(acc2[3], xx, w23.y);
            acc8 = fmaf(w8, x, acc8);
        }
        float* dst = g_p4 + ((size_t)(b * NCH4 + chunk) * NL) * HW4 + tid;
        #pragma unroll
        for (int j = 0; j < 4; j++) {
            float2 f = up2(acc2[j]);
            dst[(size_t)(2 * j)     * HW4] = f.x;
            dst[(size_t)(2 * j + 1) * HW4] = f.y;
        }
        dst[(size_t)8 * HW4] = acc8;
    } else {
        int ch3 = chunk - NCH4;
        int c0 = ch3 * 64;
        for (int i = tid; i < 64 * NL; i += 196) {
            int c = i / 9, l = i - c * 9;
            sWt[c * 12 + l] = Wl[l * C_ALL + C4 + c0 + c];
        }
        int px = tid * 4;

        ull aLo[NL], aHi[NL];                      // (px0,px1) and (px2,px3)
        #pragma unroll
        for (int l = 0; l < NL; l++) { aLo[l] = 0ull; aHi[l] = 0ull; }

        const float* x3 = l3 + ((size_t)b * C3 + c0) * HW + px;
        __syncthreads();
        #pragma unroll 4
        for (int c = 0; c < 64; c++) {
            ulonglong2 xv = *(const ulonglong2*)(x3 + (size_t)c * HW);  // LDG.128
            float4 wa = *(const float4*)&sWt[c * 12];
            float4 wb = *(const float4*)&sWt[c * 12 + 4];
            float  w8 = sWt[c * 12 + 8];
            float ws[NL] = {wa.x, wa.y, wa.z, wa.w, wb.x, wb.y, wb.z, wb.w, w8};
            #pragma unroll
            for (int l = 0; l < NL; l++) {
                ull pw = pk2(ws[l], ws[l]);
                fma2(aLo[l], xv.x, pw);
                fma2(aHi[l], xv.y, pw);
            }
        }
        float* base = g_part3 + (((size_t)ch3 * B_ + b) * NL) * HW + px;
        #pragma unroll
        for (int l = 0; l < NL; l++) {
            float2 lo = up2(aLo[l]), hi = up2(aHi[l]);
            *(float4*)(base + (size_t)l * HW) = make_float4(lo.x, lo.y, hi.x, hi.y);
        }
    }
}

// ---------------------------------------------------------------------------
// K2: reduce ab4 partials (ab3 reduction is fused into k_softmax)
// ---------------------------------------------------------------------------
__global__ void k_red() {
    int idx = blockIdx.x * 64 + threadIdx.x;
    if (idx >= B_ * NL * HW4) return;
    int b = idx / (NL * HW4), r = idx - b * (NL * HW4);
    const float* p = g_p4 + (size_t)b * NCH4 * NL * HW4 + r;
    float s = 0.f;
    #pragma unroll
    for (int ch = 0; ch < NCH4; ch++) s += p[(size_t)ch * NL * HW4];
    g_ab4[idx] = s;
}

// ---------------------------------------------------------------------------
// K3: softmax, parallel over landmarks: block = 9 warps (one per l) x 32 px.
// ---------------------------------------------------------------------------
__global__ __launch_bounds__(288) void k_softmax(float* __restrict__ out) {
    __shared__ float sL[32][10];
    int lane = threadIdx.x & 31, l = threadIdx.x >> 5;  // l = 0..8
    int g = blockIdx.x * 32 + lane;
    int b = g / HW, px = g - b * HW;
    int py = px / WW, pxx = px - py * WW;

    float cyf = 0.5f * (float)py - 0.25f;
    int iyf = (int)floorf(cyf);
    float wy = cyf - (float)iyf;
    int iy0 = iyf < 0 ? 0 : iyf;
    int iy1 = (iyf + 1) > 13 ? 13 : (iyf + 1);
    float cxf = 0.5f * (float)pxx - 0.25f;
    int ixf = (int)floorf(cxf);
    float wx = cxf - (float)ixf;
    int ix0 = ixf < 0 ? 0 : ixf;
    int ix1 = (ixf + 1) > 13 ? 13 : (ixf + 1);

    const float* r = g_ab4 + ((size_t)b * NL + l) * HW4;
    float a0 = r[iy0 * H4 + ix0], a1 = r[iy0 * H4 + ix1];
    float b0 = r[iy1 * H4 + ix0], b1 = r[iy1 * H4 + ix1];
    float t = fmaf(wx, a1 - a0, a0);
    float u = fmaf(wx, b1 - b0, b0);
    float s = fmaf(wy, u - t, t);

    #pragma unroll
    for (int ch = 0; ch < NCH3; ch++)
        s += g_part3[(((size_t)ch * B_ + b) * NL + l) * HW + px];

    float lg = 2.f * s - g_asq[l];
    sL[lane][l] = lg;
    __syncthreads();

    float m = -1e30f;
    float v[NL];
    #pragma unroll
    for (int j = 0; j < NL; j++) { v[j] = sL[lane][j]; m = fmaxf(m, v[j]); }
    float den = 0.f;
    #pragma unroll
    for (int j = 0; j < NL; j++) den += __expf(v[j] - m);

    out[MAPS_OFF + ((size_t)b * NL + l) * HW + px] = __expf(lg - m) / den;
}

// ---------------------------------------------------------------------------
// K4: adjoint-downsample of maps.
// ---------------------------------------------------------------------------
__global__ __launch_bounds__(64) void k_mapsdown(const float* __restrict__ out) {
    int idx = blockIdx.x * 64 + threadIdx.x;
    if (idx >= B_ * NL * HW4) return;
    int b = idx / (NL * HW4), r = idx - b * (NL * HW4);
    int l = r / HW4, q = r - l * HW4;
    int iy = q / H4, ix = q - iy * H4;

    const float* mp = out + MAPS_OFF + ((size_t)b * NL + l) * HW;

    float s = 0.f;
    #pragma unroll
    for (int dy = 0; dy < 4; dy++) {
        int py = 2 * iy - 1 + dy;
        if (py < 0 || py > 27) continue;
        float cy = 0.5f * (float)py - 0.25f;
        int iyf = (int)floorf(cy);
        float wy = cy - (float)iyf;
        int r0 = iyf < 0 ? 0 : iyf;
        int r1 = (iyf + 1) > 13 ? 13 : (iyf + 1);
        float wr = (r0 == iy ? 1.f - wy : 0.f) + (r1 == iy ? wy : 0.f);
        if (wr == 0.f) continue;
        #pragma unroll
        for (int dx = 0; dx < 4; dx++) {
            int pxx = 2 * ix - 1 + dx;
            if (pxx < 0 || pxx > 27) continue;
            float cx = 0.5f * (float)pxx - 0.25f;
            int ixf = (int)floorf(cx);
            float wxv = cx - (float)ixf;
            int c0 = ixf < 0 ? 0 : ixf;
            int c1 = (ixf + 1) > 13 ? 13 : (ixf + 1);
            float wc = (c0 == ix ? 1.f - wxv : 0.f) + (c1 == ix ? wxv : 0.f);
            if (wc == 0.f) continue;
            s = fmaf(wr * wc, mp[py * WW + pxx], s);
        }
    }
    g_md[idx] = s;
}

// ---------------------------------------------------------------------------
// K5: all_features (+fused modulation average), FFMA2 inner loops.
// Thread = one channel, 9 packed accumulators (even/odd px pairs).
// ---------------------------------------------------------------------------
__global__ __launch_bounds__(128) void k_feat(const float* __restrict__ l3,
                                              const float* __restrict__ l4,
                                              const float* __restrict__ mod,
                                              float* __restrict__ out) {
    __shared__ float4 sM[NL * 196];   // up to 9 x 784 floats (28.2 KB)

    int b = blockIdx.y, cg = blockIdx.x, tid = threadIdx.x;

    ull accP[NL];
    #pragma unroll
    for (int l = 0; l < NL; l++) accP[l] = 0ull;

    int cglobal;

    if (cg < 16) {
        int c = cg * 128 + tid;
        cglobal = c;
        const float4* md4 = (const float4*)(g_md + (size_t)b * NL * HW4);
        for (int i = tid; i < NL * 49; i += 128) sM[i] = md4[i];
        __syncthreads();

        const ulonglong2* xr = (const ulonglong2*)(l4 + ((size_t)b * C4 + c) * HW4);
        const ulonglong2* sM2 = (const ulonglong2*)sM;
        #pragma unroll 7
        for (int i = 0; i < 49; i++) {
            ulonglong2 x = xr[i];
            #pragma unroll
            for (int l = 0; l < NL; l++) {
                ulonglong2 m = sM2[l * 49 + i];
                fma2(accP[l], x.x, m.x);
                fma2(accP[l], x.y, m.y);
            }
        }
    } else {
        int c = (cg - 16) * 128 + tid;   // within l3
        cglobal = C4 + c;
        const float4* mp4 = (const float4*)(out + MAPS_OFF + (size_t)b * NL * HW);
        for (int i = tid; i < NL * 196; i += 128) sM[i] = mp4[i];
        __syncthreads();

        const ulonglong2* xr = (const ulonglong2*)(l3 + ((size_t)b * C3 + c) * HW);
        const ulonglong2* sM2 = (const ulonglong2*)sM;
        #pragma unroll 4
        for (int i = 0; i < 196; i++) {
            ulonglong2 x = xr[i];
            #pragma unroll
            for (int l = 0; l < NL; l++) {
                ulonglong2 m = sM2[l * 196 + i];
                fma2(accP[l], x.x, m.x);
                fma2(accP[l], x.y, m.y);
            }
        }
    }

    const float sc = 1.0f / (float)HW;
    float* fo = out + FEAT_OFF + ((size_t)b * C_ALL + cglobal) * NL;
    float mv = 0.f;
    #pragma unroll
    for (int l = 0; l < NL; l++) {
        float2 f = up2(accP[l]);
        float r = (f.x + f.y) * sc;
        fo[l] = r;
        if (l < 8) mv = fmaf(r, mod[cglobal * NL + l], mv);
    }
    g_modavg[(size_t)cglobal * B_ + b] = mv * 0.125f;
}

// ---------------------------------------------------------------------------
// K6: class_scores[b,k] = sum_c W_class[k,c] * mod_avg[c][b], FFMA2.
// ---------------------------------------------------------------------------
__global__ __launch_bounds__(256) void k_cls(const float* __restrict__ Wc,
                                             float* __restrict__ out) {
    int k = blockIdx.x, tid = threadIdx.x, warp = tid >> 5, lane = tid & 31;
    const float* wr = Wc + (size_t)k * C_ALL;

    ull acc2[8];
    #pragma unroll
    for (int j = 0; j < 8; j++) acc2[j] = 0ull;

    for (int c = tid; c < C_ALL; c += 256) {
        float w = wr[c];
        ull ww = pk2(w, w);
        const ulonglong2* mv = (const ulonglong2*)(g_modavg + (size_t)c * B_);
        #pragma unroll
        for (int q = 0; q < 4; q++) {
            ulonglong2 m = mv[q];
            fma2(acc2[2 * q],     ww, m.x);
            fma2(acc2[2 * q + 1], ww, m.y);
        }
    }

    float acc[B_];
    #pragma unroll
    for (int j = 0; j < 8; j++) {
        float2 f = up2(acc2[j]);
        acc[2 * j] = f.x;
        acc[2 * j + 1] = f.y;
    }

    __shared__ float red[8][B_];
    #pragma unroll
    for (int b = 0; b < B_; b++) {
        float v = acc[b];
        #pragma unroll
        for (int o = 16; o; o >>= 1) v += __shfl_xor_sync(0xffffffffu, v, o);
        acc[b] = v;
    }
    if (lane == 0)
        #pragma unroll
        for (int b = 0; b < B_; b++) red[warp][b] = acc[b];
    __syncthreads();
    if (tid < B_) {
        float s = 0.f;
        #pragma unroll
        for (int w = 0; w < 8; w++) s += red[w][tid];
        out[(size_t)tid * NK + k] = s;
    }
}

// ---------------------------------------------------------------------------
extern "C" void kernel_launch(void* const* d_in, const int* in_sizes, int n_in,
                              void* d_out, int out_size) {
    const float* l3  = (const float*)d_in[0];
    const float* l4  = (const float*)d_in[1];
    const float* Wl  = (const float*)d_in[2];
    const float* Wc  = (const float*)d_in[3];
    const float* mod = (const float*)d_in[4];
    float* out = (float*)d_out;

    k_asq<<<NL, 256>>>(Wl);
    k_ab<<<dim3(NCH4 + NCH3, B_), 196>>>(l3, l4, Wl);
    k_red<<<(B_ * NL * HW4 + 63) / 64, 64>>>();
    k_softmax<<<(B_ * HW) / 32, 288>>>(out);
    k_mapsdown<<<(B_ * NL * HW4 + 63) / 64, 64>>>(out);
    k_feat<<<dim3(24, B_), 128>>>(l3, l4, mod, out);
    k_cls<<<NK, 256>>>(Wc, out);
}

// round 13
// speedup vs baseline: 1.6147x; 1.1835x over previous
#include <cuda_runtime.h>
#include <math.h>

// Problem constants
#define B_     16
#define HH     28
#define WW     28
#define HW     784
#define C_ALL  3072
#define C4     2048
#define C3     1024
#define H4     14
#define HW4    196
#define NL     9
#define NK     2000

#define NCH4   32   // l4 chunks (64 ch each) over 2048, contraction at 14x14
#define NCH3   16   // l3 chunks (64 ch each) over 1024, contraction at 28x28

// Output layout
#define CLS_OFF  0
#define MAPS_OFF (B_*NK)                  // 32000
#define FEAT_OFF (MAPS_OFF + B_*NL*HW)    // 144896

typedef unsigned long long ull;

// packed f32x2 helpers (ptxas never emits FFMA2 from C++; PTX required)
__device__ __forceinline__ ull pk2(float lo, float hi) {
    ull r; asm("mov.b64 %0, {%1, %2};" : "=l"(r) : "f"(lo), "f"(hi)); return r;
}
__device__ __forceinline__ void fma2(ull& d, ull a, ull b) {
    asm("fma.rn.f32x2 %0, %1, %2, %0;" : "+l"(d) : "l"(a), "l"(b));
}
__device__ __forceinline__ float2 up2(ull v) {
    float2 f; asm("mov.b64 {%0, %1}, %2;" : "=f"(f.x), "=f"(f.y) : "l"(v)); return f;
}

// Scratch (static __device__ arrays: allocation-free)
__device__ float g_asq[NL];
__device__ float g_p4[(size_t)B_*NCH4*NL*HW4];        // partial ab4 [b][ch][l][q]
__device__ float g_part3[(size_t)NCH3*B_*NL*HW];      // partial ab3 [ch][b][l][px]
__device__ float g_ab4[(size_t)B_*NL*HW4];            // summed ab4 (14x14)
__device__ float g_md[(size_t)B_*NL*HW4];             // adjoint-downsampled maps
__device__ float g_modavg[(size_t)B_*C_ALL];          // [b][c]  (transposed!)

// ---------------------------------------------------------------------------
// K0: a_sq[l] = ||W_land[l]||^2  (one block per landmark)
// ---------------------------------------------------------------------------
__global__ void k_asq(const float* __restrict__ Wl) {
    int l = blockIdx.x, tid = threadIdx.x, warp = tid >> 5, lane = tid & 31;
    __shared__ float red[8];
    float s = 0.f;
    for (int i = tid; i < C_ALL; i += 256) {
        float w = Wl[l * C_ALL + i];
        s = fmaf(w, w, s);
    }
    #pragma unroll
    for (int o = 16; o; o >>= 1) s += __shfl_xor_sync(0xffffffffu, s, o);
    if (lane == 0) red[warp] = s;
    __syncthreads();
    if (tid == 0) {
        float t = 0.f;
        #pragma unroll
        for (int w = 0; w < 8; w++) t += red[w];
        g_asq[l] = t;
    }
}

// ---------------------------------------------------------------------------
// K1: fused landmark-logit contraction (64-ch chunks, 768 blocks), FFMA2.
// ---------------------------------------------------------------------------
__global__ __launch_bounds__(196) void k_ab(const float* __restrict__ l3,
                                            const float* __restrict__ l4,
                                            const float* __restrict__ Wl) {
    __shared__ __align__(16) float sWt[64 * 12];   // [c][l] padded to 12

    int b = blockIdx.y, chunk = blockIdx.x, tid = threadIdx.x;

    if (chunk < NCH4) {
        int c0 = chunk * 64;
        for (int i = tid; i < 64 * NL; i += 196) {
            int c = i / 9, l = i - c * 9;
            sWt[c * 12 + l] = Wl[l * C_ALL + c0 + c];
        }
        const float* l4b = l4 + ((size_t)b * C4 + c0) * HW4 + tid;

        ull acc2[4] = {0ull, 0ull, 0ull, 0ull};   // (l0,l1)(l2,l3)(l4,l5)(l6,l7)
        float acc8 = 0.f;

        __syncthreads();
        #pragma unroll 8
        for (int c = 0; c < 64; c++) {
            float x = l4b[(size_t)c * HW4];        // coalesced LDG.32
            ull xx = pk2(x, x);
            const ulonglong2* wp = (const ulonglong2*)&sWt[c * 12];
            ulonglong2 w01 = wp[0];
            ulonglong2 w23 = wp[1];
            float w8 = sWt[c * 12 + 8];
            fma2(acc2[0], xx, w01.x);
            fma2(acc2[1], xx, w01.y);
            fma2(acc2[2], xx, w23.x);
            fma2(acc2[3], xx, w23.y);
            acc8 = fmaf(w8, x, acc8);
        }
        float* dst = g_p4 + ((size_t)(b * NCH4 + chunk) * NL) * HW4 + tid;
        #pragma unroll
        for (int j = 0; j < 4; j++) {
            float2 f = up2(acc2[j]);
            dst[(size_t)(2 * j)     * HW4] = f.x;
            dst[(size_t)(2 * j + 1) * HW4] = f.y;
        }
        dst[(size_t)8 * HW4] = acc8;
    } else {
        int ch3 = chunk - NCH4;
        int c0 = ch3 * 64;
        for (int i = tid; i < 64 * NL; i += 196) {
            int c = i / 9, l = i - c * 9;
            sWt[c * 12 + l] = Wl[l * C_ALL + C4 + c0 + c];
        }
        int px = tid * 4;

        ull aLo[NL], aHi[NL];                      // (px0,px1) and (px2,px3)
        #pragma unroll
        for (int l = 0; l < NL; l++) { aLo[l] = 0ull; aHi[l] = 0ull; }

        const float* x3 = l3 + ((size_t)b * C3 + c0) * HW + px;
        __syncthreads();
        #pragma unroll 8
        for (int c = 0; c < 64; c++) {
            ulonglong2 xv = *(const ulonglong2*)(x3 + (size_t)c * HW);  // LDG.128
            float4 wa = *(const float4*)&sWt[c * 12];
            float4 wb = *(const float4*)&sWt[c * 12 + 4];
            float  w8 = sWt[c * 12 + 8];
            float ws[NL] = {wa.x, wa.y, wa.z, wa.w, wb.x, wb.y, wb.z, wb.w, w8};
            #pragma unroll
            for (int l = 0; l < NL; l++) {
                ull pw = pk2(ws[l], ws[l]);
                fma2(aLo[l], xv.x, pw);
                fma2(aHi[l], xv.y, pw);
            }
        }
        float* base = g_part3 + (((size_t)ch3 * B_ + b) * NL) * HW + px;
        #pragma unroll
        for (int l = 0; l < NL; l++) {
            float2 lo = up2(aLo[l]), hi = up2(aHi[l]);
            *(float4*)(base + (size_t)l * HW) = make_float4(lo.x, lo.y, hi.x, hi.y);
        }
    }
}

// ---------------------------------------------------------------------------
// K2: reduce ab4 partials (ab3 reduction is fused into k_softmax)
// ---------------------------------------------------------------------------
__global__ void k_red() {
    int idx = blockIdx.x * 64 + threadIdx.x;
    if (idx >= B_ * NL * HW4) return;
    int b = idx / (NL * HW4), r = idx - b * (NL * HW4);
    const float* p = g_p4 + (size_t)b * NCH4 * NL * HW4 + r;
    float s = 0.f;
    #pragma unroll
    for (int ch = 0; ch < NCH4; ch++) s += p[(size_t)ch * NL * HW4];
    g_ab4[idx] = s;
}

// ---------------------------------------------------------------------------
// K3: softmax, parallel over landmarks: block = 9 warps (one per l) x 32 px.
// ---------------------------------------------------------------------------
__global__ __launch_bounds__(288) void k_softmax(float* __restrict__ out) {
    __shared__ float sL[32][10];
    int lane = threadIdx.x & 31, l = threadIdx.x >> 5;  // l = 0..8
    int g = blockIdx.x * 32 + lane;
    int b = g / HW, px = g - b * HW;
    int py = px / WW, pxx = px - py * WW;

    float cyf = 0.5f * (float)py - 0.25f;
    int iyf = (int)floorf(cyf);
    float wy = cyf - (float)iyf;
    int iy0 = iyf < 0 ? 0 : iyf;
    int iy1 = (iyf + 1) > 13 ? 13 : (iyf + 1);
    float cxf = 0.5f * (float)pxx - 0.25f;
    int ixf = (int)floorf(cxf);
    float wx = cxf - (float)ixf;
    int ix0 = ixf < 0 ? 0 : ixf;
    int ix1 = (ixf + 1) > 13 ? 13 : (ixf + 1);

    const float* r = g_ab4 + ((size_t)b * NL + l) * HW4;
    float a0 = r[iy0 * H4 + ix0], a1 = r[iy0 * H4 + ix1];
    float b0 = r[iy1 * H4 + ix0], b1 = r[iy1 * H4 + ix1];
    float t = fmaf(wx, a1 - a0, a0);
    float u = fmaf(wx, b1 - b0, b0);
    float s = fmaf(wy, u - t, t);

    #pragma unroll
    for (int ch = 0; ch < NCH3; ch++)
        s += g_part3[(((size_t)ch * B_ + b) * NL + l) * HW + px];

    float lg = 2.f * s - g_asq[l];
    sL[lane][l] = lg;
    __syncthreads();

    float m = -1e30f;
    float v[NL];
    #pragma unroll
    for (int j = 0; j < NL; j++) { v[j] = sL[lane][j]; m = fmaxf(m, v[j]); }
    float den = 0.f;
    #pragma unroll
    for (int j = 0; j < NL; j++) den += __expf(v[j] - m);

    out[MAPS_OFF + ((size_t)b * NL + l) * HW + px] = __expf(lg - m) / den;
}

// ---------------------------------------------------------------------------
// K4: adjoint-downsample of maps.
// ---------------------------------------------------------------------------
__global__ __launch_bounds__(64) void k_mapsdown(const float* __restrict__ out) {
    int idx = blockIdx.x * 64 + threadIdx.x;
    if (idx >= B_ * NL * HW4) return;
    int b = idx / (NL * HW4), r = idx - b * (NL * HW4);
    int l = r / HW4, q = r - l * HW4;
    int iy = q / H4, ix = q - iy * H4;

    const float* mp = out + MAPS_OFF + ((size_t)b * NL + l) * HW;

    float s = 0.f;
    #pragma unroll
    for (int dy = 0; dy < 4; dy++) {
        int py = 2 * iy - 1 + dy;
        if (py < 0 || py > 27) continue;
        float cy = 0.5f * (float)py - 0.25f;
        int iyf = (int)floorf(cy);
        float wy = cy - (float)iyf;
        int r0 = iyf < 0 ? 0 : iyf;
        int r1 = (iyf + 1) > 13 ? 13 : (iyf + 1);
        float wr = (r0 == iy ? 1.f - wy : 0.f) + (r1 == iy ? wy : 0.f);
        if (wr == 0.f) continue;
        #pragma unroll
        for (int dx = 0; dx < 4; dx++) {
            int pxx = 2 * ix - 1 + dx;
            if (pxx < 0 || pxx > 27) continue;
            float cx = 0.5f * (float)pxx - 0.25f;
            int ixf = (int)floorf(cx);
            float wxv = cx - (float)ixf;
            int c0 = ixf < 0 ? 0 : ixf;
            int c1 = (ixf + 1) > 13 ? 13 : (ixf + 1);
            float wc = (c0 == ix ? 1.f - wxv : 0.f) + (c1 == ix ? wxv : 0.f);
            if (wc == 0.f) continue;
            s = fmaf(wr * wc, mp[py * WW + pxx], s);
        }
    }
    g_md[idx] = s;
}

// ---------------------------------------------------------------------------
// K5: all_features (+fused modulation average), FFMA2 inner loops.
// Thread = one channel, 9 packed accumulators (even/odd px pairs).
// modavg written transposed [b][c] -> coalesced store.
// ---------------------------------------------------------------------------
__global__ __launch_bounds__(128) void k_feat(const float* __restrict__ l3,
                                              const float* __restrict__ l4,
                                              const float* __restrict__ mod,
                                              float* __restrict__ out) {
    __shared__ float4 sM[NL * 196];   // up to 9 x 784 floats (28.2 KB)

    int b = blockIdx.y, cg = blockIdx.x, tid = threadIdx.x;

    ull accP[NL];
    #pragma unroll
    for (int l = 0; l < NL; l++) accP[l] = 0ull;

    int cglobal;

    if (cg < 16) {
        int c = cg * 128 + tid;
        cglobal = c;
        const float4* md4 = (const float4*)(g_md + (size_t)b * NL * HW4);
        for (int i = tid; i < NL * 49; i += 128) sM[i] = md4[i];
        __syncthreads();

        const ulonglong2* xr = (const ulonglong2*)(l4 + ((size_t)b * C4 + c) * HW4);
        const ulonglong2* sM2 = (const ulonglong2*)sM;
        #pragma unroll 7
        for (int i = 0; i < 49; i++) {
            ulonglong2 x = xr[i];
            #pragma unroll
            for (int l = 0; l < NL; l++) {
                ulonglong2 m = sM2[l * 49 + i];
                fma2(accP[l], x.x, m.x);
                fma2(accP[l], x.y, m.y);
            }
        }
    } else {
        int c = (cg - 16) * 128 + tid;   // within l3
        cglobal = C4 + c;
        const float4* mp4 = (const float4*)(out + MAPS_OFF + (size_t)b * NL * HW);
        for (int i = tid; i < NL * 196; i += 128) sM[i] = mp4[i];
        __syncthreads();

        const ulonglong2* xr = (const ulonglong2*)(l3 + ((size_t)b * C3 + c) * HW);
        const ulonglong2* sM2 = (const ulonglong2*)sM;
        #pragma unroll 7
        for (int i = 0; i < 196; i++) {
            ulonglong2 x = xr[i];
            #pragma unroll
            for (int l = 0; l < NL; l++) {
                ulonglong2 m = sM2[l * 196 + i];
                fma2(accP[l], x.x, m.x);
                fma2(accP[l], x.y, m.y);
            }
        }
    }

    const float sc = 1.0f / (float)HW;
    float* fo = out + FEAT_OFF + ((size_t)b * C_ALL + cglobal) * NL;
    float mv = 0.f;
    #pragma unroll
    for (int l = 0; l < NL; l++) {
        float2 f = up2(accP[l]);
        float r = (f.x + f.y) * sc;
        fo[l] = r;
        if (l < 8) mv = fmaf(r, mod[cglobal * NL + l], mv);
    }
    g_modavg[(size_t)b * C_ALL + cglobal] = mv * 0.125f;   // coalesced
}

// ---------------------------------------------------------------------------
// K6: class_scores[b,k] = sum_c W_class[k,c] * mod_avg[b][c].
// 16 fully coalesced LDG.32 per channel (1 wavefront each, deep MLP).
// ---------------------------------------------------------------------------
__global__ __launch_bounds__(256) void k_cls(const float* __restrict__ Wc,
                                             float* __restrict__ out) {
    int k = blockIdx.x, tid = threadIdx.x, warp = tid >> 5, lane = tid & 31;
    const float* wr = Wc + (size_t)k * C_ALL;

    float acc[B_];
    #pragma unroll
    for (int b = 0; b < B_; b++) acc[b] = 0.f;

    for (int c = tid; c < C_ALL; c += 256) {
        float w = wr[c];
        #pragma unroll
        for (int b = 0; b < B_; b++)
            acc[b] = fmaf(w, g_modavg[(size_t)b * C_ALL + c], acc[b]);
    }

    __shared__ float red[8][B_];
    #pragma unroll
    for (int b = 0; b < B_; b++) {
        float v = acc[b];
        #pragma unroll
        for (int o = 16; o; o >>= 1) v += __shfl_xor_sync(0xffffffffu, v, o);
        acc[b] = v;
    }
    if (lane == 0)
        #pragma unroll
        for (int b = 0; b < B_; b++) red[warp][b] = acc[b];
    __syncthreads();
    if (tid < B_) {
        float s = 0.f;
        #pragma unroll
        for (int w = 0; w < 8; w++) s += red[w][tid];
        out[(size_t)tid * NK + k] = s;
    }
}

// ---------------------------------------------------------------------------
extern "C" void kernel_launch(void* const* d_in, const int* in_sizes, int n_in,
                              void* d_out, int out_size) {
    const float* l3  = (const float*)d_in[0];
    const float* l4  = (const float*)d_in[1];
    const float* Wl  = (const float*)d_in[2];
    const float* Wc  = (const float*)d_in[3];
    const float* mod = (const float*)d_in[4];
    float* out = (float*)d_out;

    k_asq<<<NL, 256>>>(Wl);
    k_ab<<<dim3(NCH4 + NCH3, B_), 196>>>(l3, l4, Wl);
    k_red<<<(B_ * NL * HW4 + 63) / 64, 64>>>();
    k_softmax<<<(B_ * HW) / 32, 288>>>(out);
    k_mapsdown<<<(B_ * NL * HW4 + 63) / 64, 64>>>(out);
    k_feat<<<dim3(24, B_), 128>>>(l3, l4, mod, out);
    k_cls<<<NK, 256>>>(Wc, out);
}

// round 15
// speedup vs baseline: 1.6719x; 1.0354x over previous
#include <cuda_runtime.h>
#include <math.h>

// Problem constants
#define B_     16
#define HH     28
#define WW     28
#define HW     784
#define C_ALL  3072
#define C4     2048
#define C3     1024
#define H4     14
#define HW4    196
#define NL     9
#define NK     2000

#define NCH4   32   // l4 chunks (64 ch each) over 2048, contraction at 14x14
#define NCH3   16   // l3 chunks (64 ch each) over 1024, contraction at 28x28

// Output layout
#define CLS_OFF  0
#define MAPS_OFF (B_*NK)                  // 32000
#define FEAT_OFF (MAPS_OFF + B_*NL*HW)    // 144896

typedef unsigned long long ull;

// packed f32x2 helpers (ptxas never emits FFMA2 from C++; PTX required)
__device__ __forceinline__ ull pk2(float lo, float hi) {
    ull r; asm("mov.b64 %0, {%1, %2};" : "=l"(r) : "f"(lo), "f"(hi)); return r;
}
__device__ __forceinline__ void fma2(ull& d, ull a, ull b) {
    asm("fma.rn.f32x2 %0, %1, %2, %0;" : "+l"(d) : "l"(a), "l"(b));
}
__device__ __forceinline__ float2 up2(ull v) {
    float2 f; asm("mov.b64 {%0, %1}, %2;" : "=f"(f.x), "=f"(f.y) : "l"(v)); return f;
}

// Scratch (static __device__ arrays: allocation-free)
__device__ float g_asq[NL];
__device__ float g_p4[(size_t)B_*NCH4*NL*HW4];        // partial ab4 [b][ch][l][q]
__device__ float g_part3[(size_t)NCH3*B_*NL*HW];      // partial ab3 [ch][b][l][px]
__device__ float g_ab4[(size_t)B_*NL*HW4];            // summed ab4 (14x14)
__device__ float g_md[(size_t)B_*NL*HW4];             // adjoint-downsampled maps
__device__ float g_modavg[(size_t)B_*C_ALL];          // [b][c]  (transposed)

// ---------------------------------------------------------------------------
// K0: a_sq[l] = ||W_land[l]||^2  (one block per landmark)
// ---------------------------------------------------------------------------
__global__ void k_asq(const float* __restrict__ Wl) {
    int l = blockIdx.x, tid = threadIdx.x, warp = tid >> 5, lane = tid & 31;
    __shared__ float red[8];
    float s = 0.f;
    for (int i = tid; i < C_ALL; i += 256) {
        float w = Wl[l * C_ALL + i];
        s = fmaf(w, w, s);
    }
    #pragma unroll
    for (int o = 16; o; o >>= 1) s += __shfl_xor_sync(0xffffffffu, s, o);
    if (lane == 0) red[warp] = s;
    __syncthreads();
    if (tid == 0) {
        float t = 0.f;
        #pragma unroll
        for (int w = 0; w < 8; w++) t += red[w];
        g_asq[l] = t;
    }
}

// ---------------------------------------------------------------------------
// K1: fused landmark-logit contraction (64-ch chunks, 768 blocks), FFMA2.
// ---------------------------------------------------------------------------
__global__ __launch_bounds__(196) void k_ab(const float* __restrict__ l3,
                                            const float* __restrict__ l4,
                                            const float* __restrict__ Wl) {
    __shared__ __align__(16) float sWt[64 * 12];   // [c][l] padded to 12

    int b = blockIdx.y, chunk = blockIdx.x, tid = threadIdx.x;

    if (chunk < NCH4) {
        int c0 = chunk * 64;
        for (int i = tid; i < 64 * NL; i += 196) {
            int c = i / 9, l = i - c * 9;
            sWt[c * 12 + l] = Wl[l * C_ALL + c0 + c];
        }
        const float* l4b = l4 + ((size_t)b * C4 + c0) * HW4 + tid;

        ull acc2[4] = {0ull, 0ull, 0ull, 0ull};
        float acc8 = 0.f;

        __syncthreads();
        #pragma unroll 16
        for (int c = 0; c < 64; c++) {
            float x = l4b[(size_t)c * HW4];        // coalesced LDG.32
            ull xx = pk2(x, x);
            const ulonglong2* wp = (const ulonglong2*)&sWt[c * 12];
            ulonglong2 w01 = wp[0];
            ulonglong2 w23 = wp[1];
            float w8 = sWt[c * 12 + 8];
            fma2(acc2[0], xx, w01.x);
            fma2(acc2[1], xx, w01.y);
            fma2(acc2[2], xx, w23.x);
            fma2(acc2[3], xx, w23.y);
            acc8 = fmaf(w8, x, acc8);
        }
        float* dst = g_p4 + ((size_t)(b * NCH4 + chunk) * NL) * HW4 + tid;
        #pragma unroll
        for (int j = 0; j < 4; j++) {
            float2 f = up2(acc2[j]);
            dst[(size_t)(2 * j)     * HW4] = f.x;
            dst[(size_t)(2 * j + 1) * HW4] = f.y;
        }
        dst[(size_t)8 * HW4] = acc8;
    } else {
        int ch3 = chunk - NCH4;
        int c0 = ch3 * 64;
        for (int i = tid; i < 64 * NL; i += 196) {
            int c = i / 9, l = i - c * 9;
            sWt[c * 12 + l] = Wl[l * C_ALL + C4 + c0 + c];
        }
        int px = tid * 4;

        ull aLo[NL], aHi[NL];
        #pragma unroll
        for (int l = 0; l < NL; l++) { aLo[l] = 0ull; aHi[l] = 0ull; }

        const float* x3 = l3 + ((size_t)b * C3 + c0) * HW + px;
        __syncthreads();
        #pragma unroll 8
        for (int c = 0; c < 64; c++) {
            ulonglong2 xv = *(const ulonglong2*)(x3 + (size_t)c * HW);  // LDG.128
            float4 wa = *(const float4*)&sWt[c * 12];
            float4 wb = *(const float4*)&sWt[c * 12 + 4];
            float  w8 = sWt[c * 12 + 8];
            float ws[NL] = {wa.x, wa.y, wa.z, wa.w, wb.x, wb.y, wb.z, wb.w, w8};
            #pragma unroll
            for (int l = 0; l < NL; l++) {
                ull pw = pk2(ws[l], ws[l]);
                fma2(aLo[l], xv.x, pw);
                fma2(aHi[l], xv.y, pw);
            }
        }
        float* base = g_part3 + (((size_t)ch3 * B_ + b) * NL) * HW + px;
        #pragma unroll
        for (int l = 0; l < NL; l++) {
            float2 lo = up2(aLo[l]), hi = up2(aHi[l]);
            *(float4*)(base + (size_t)l * HW) = make_float4(lo.x, lo.y, hi.x, hi.y);
        }
    }
}

// ---------------------------------------------------------------------------
// K2: reduce ab4 partials (ab3 reduction is fused into k_softmax)
// ---------------------------------------------------------------------------
__global__ void k_red() {
    int idx = blockIdx.x * 64 + threadIdx.x;
    if (idx >= B_ * NL * HW4) return;
    int b = idx / (NL * HW4), r = idx - b * (NL * HW4);
    const float* p = g_p4 + (size_t)b * NCH4 * NL * HW4 + r;
    float s = 0.f;
    #pragma unroll
    for (int ch = 0; ch < NCH4; ch++) s += p[(size_t)ch * NL * HW4];
    g_ab4[idx] = s;
}

// ---------------------------------------------------------------------------
// K3: softmax, parallel over landmarks: block = 9 warps (one per l) x 32 px.
// ---------------------------------------------------------------------------
__global__ __launch_bounds__(288) void k_softmax(float* __restrict__ out) {
    __shared__ float sL[32][10];
    int lane = threadIdx.x & 31, l = threadIdx.x >> 5;  // l = 0..8
    int g = blockIdx.x * 32 + lane;
    int b = g / HW, px = g - b * HW;
    int py = px / WW, pxx = px - py * WW;

    float cyf = 0.5f * (float)py - 0.25f;
    int iyf = (int)floorf(cyf);
    float wy = cyf - (float)iyf;
    int iy0 = iyf < 0 ? 0 : iyf;
    int iy1 = (iyf + 1) > 13 ? 13 : (iyf + 1);
    float cxf = 0.5f * (float)pxx - 0.25f;
    int ixf = (int)floorf(cxf);
    float wx = cxf - (float)ixf;
    int ix0 = ixf < 0 ? 0 : ixf;
    int ix1 = (ixf + 1) > 13 ? 13 : (ixf + 1);

    const float* r = g_ab4 + ((size_t)b * NL + l) * HW4;
    float a0 = r[iy0 * H4 + ix0], a1 = r[iy0 * H4 + ix1];
    float b0 = r[iy1 * H4 + ix0], b1 = r[iy1 * H4 + ix1];
    float t = fmaf(wx, a1 - a0, a0);
    float u = fmaf(wx, b1 - b0, b0);
    float s = fmaf(wy, u - t, t);

    #pragma unroll
    for (int ch = 0; ch < NCH3; ch++)
        s += g_part3[(((size_t)ch * B_ + b) * NL + l) * HW + px];

    float lg = 2.f * s - g_asq[l];
    sL[lane][l] = lg;
    __syncthreads();

    float m = -1e30f;
    float v[NL];
    #pragma unroll
    for (int j = 0; j < NL; j++) { v[j] = sL[lane][j]; m = fmaxf(m, v[j]); }
    float den = 0.f;
    #pragma unroll
    for (int j = 0; j < NL; j++) den += __expf(v[j] - m);

    out[MAPS_OFF + ((size_t)b * NL + l) * HW + px] = __expf(lg - m) / den;
}

// ---------------------------------------------------------------------------
// K4: adjoint-downsample of maps.
// ---------------------------------------------------------------------------
__global__ __launch_bounds__(64) void k_mapsdown(const float* __restrict__ out) {
    int idx = blockIdx.x * 64 + threadIdx.x;
    if (idx >= B_ * NL * HW4) return;
    int b = idx / (NL * HW4), r = idx - b * (NL * HW4);
    int l = r / HW4, q = r - l * HW4;
    int iy = q / H4, ix = q - iy * H4;

    const float* mp = out + MAPS_OFF + ((size_t)b * NL + l) * HW;

    float s = 0.f;
    #pragma unroll
    for (int dy = 0; dy < 4; dy++) {
        int py = 2 * iy - 1 + dy;
        if (py < 0 || py > 27) continue;
        float cy = 0.5f * (float)py - 0.25f;
        int iyf = (int)floorf(cy);
        float wy = cy - (float)iyf;
        int r0 = iyf < 0 ? 0 : iyf;
        int r1 = (iyf + 1) > 13 ? 13 : (iyf + 1);
        float wr = (r0 == iy ? 1.f - wy : 0.f) + (r1 == iy ? wy : 0.f);
        if (wr == 0.f) continue;
        #pragma unroll
        for (int dx = 0; dx < 4; dx++) {
            int pxx = 2 * ix - 1 + dx;
            if (pxx < 0 || pxx > 27) continue;
            float cx = 0.5f * (float)pxx - 0.25f;
            int ixf = (int)floorf(cx);
            float wxv = cx - (float)ixf;
            int c0 = ixf < 0 ? 0 : ixf;
            int c1 = (ixf + 1) > 13 ? 13 : (ixf + 1);
            float wc = (c0 == ix ? 1.f - wxv : 0.f) + (c1 == ix ? wxv : 0.f);
            if (wc == 0.f) continue;
            s = fmaf(wr * wc, mp[py * WW + pxx], s);
        }
    }
    g_md[idx] = s;
}

// ---------------------------------------------------------------------------
// K5: all_features (+fused modulation average), FFMA2, px-SPLIT blocks.
// 256 threads: cl = tid&127 -> channel, half = tid>>7 -> px range half.
// grid.x = 24: cg<16 -> l4 (16*128=2048 ch), cg in 16..23 -> l3 (8*128=1024).
// ---------------------------------------------------------------------------
__global__ __launch_bounds__(256) void k_feat(const float* __restrict__ l3,
                                              const float* __restrict__ l4,
                                              const float* __restrict__ mod,
                                              float* __restrict__ out) {
    __shared__ float4 sM[NL * 196];   // up to 9 x 784 floats (28.2 KB)
    __shared__ float  sF[128 * 10];   // 5 KB partial sums from half 1

    int b = blockIdx.y, cg = blockIdx.x, tid = threadIdx.x;
    int cl = tid & 127, half = tid >> 7;

    ull accP[NL];
    #pragma unroll
    for (int l = 0; l < NL; l++) accP[l] = 0ull;

    int cglobal;

    if (cg < 16) {
        int c = cg * 128 + cl;
        cglobal = c;
        const float4* md4 = (const float4*)(g_md + (size_t)b * NL * HW4);
        for (int i = tid; i < NL * 49; i += 256) sM[i] = md4[i];
        __syncthreads();

        const ulonglong2* xr = (const ulonglong2*)(l4 + ((size_t)b * C4 + c) * HW4);
        const ulonglong2* sM2 = (const ulonglong2*)sM;
        int i0 = half ? 25 : 0, i1 = half ? 49 : 25;
        #pragma unroll 5
        for (int i = i0; i < i1; i++) {
            ulonglong2 x = xr[i];
            #pragma unroll
            for (int l = 0; l < NL; l++) {
                ulonglong2 m = sM2[l * 49 + i];
                fma2(accP[l], x.x, m.x);
                fma2(accP[l], x.y, m.y);
            }
        }
    } else {
        int c = (cg - 16) * 128 + cl;   // within l3 (cg 16..23 -> c < 1024)
        cglobal = C4 + c;
        const float4* mp4 = (const float4*)(out + MAPS_OFF + (size_t)b * NL * HW);
        for (int i = tid; i < NL * 196; i += 256) sM[i] = mp4[i];
        __syncthreads();

        const ulonglong2* xr = (const ulonglong2*)(l3 + ((size_t)b * C3 + c) * HW);
        const ulonglong2* sM2 = (const ulonglong2*)sM;
        int i0 = half * 98, i1 = i0 + 98;
        #pragma unroll 7
        for (int i = i0; i < i1; i++) {
            ulonglong2 x = xr[i];
            #pragma unroll
            for (int l = 0; l < NL; l++) {
                ulonglong2 m = sM2[l * 196 + i];
                fma2(accP[l], x.x, m.x);
                fma2(accP[l], x.y, m.y);
            }
        }
    }

    if (half) {
        #pragma unroll
        for (int l = 0; l < NL; l++) {
            float2 f = up2(accP[l]);
            sF[cl * 10 + l] = f.x + f.y;
        }
    }
    __syncthreads();
    if (!half) {
        const float sc = 1.0f / (float)HW;
        float* fo = out + FEAT_OFF + ((size_t)b * C_ALL + cglobal) * NL;
        float mv = 0.f;
        #pragma unroll
        for (int l = 0; l < NL; l++) {
            float2 f = up2(accP[l]);
            float r = (f.x + f.y + sF[cl * 10 + l]) * sc;
            fo[l] = r;
            if (l < 8) mv = fmaf(r, mod[cglobal * NL + l], mv);
        }
        g_modavg[(size_t)b * C_ALL + cglobal] = mv * 0.125f;   // coalesced
    }
}

// ---------------------------------------------------------------------------
// K6: class_scores[b,k] = sum_c W_class[k,c] * mod_avg[b][c].
// 16 fully coalesced LDG.32 per channel, unroll 2 for deeper MLP.
// ---------------------------------------------------------------------------
__global__ __launch_bounds__(256) void k_cls(const float* __restrict__ Wc,
                                             float* __restrict__ out) {
    int k = blockIdx.x, tid = threadIdx.x, warp = tid >> 5, lane = tid & 31;
    const float* wr = Wc + (size_t)k * C_ALL;

    float acc[B_];
    #pragma unroll
    for (int b = 0; b < B_; b++) acc[b] = 0.f;

    #pragma unroll 2
    for (int c = tid; c < C_ALL; c += 256) {
        float w = wr[c];
        #pragma unroll
        for (int b = 0; b < B_; b++)
            acc[b] = fmaf(w, g_modavg[(size_t)b * C_ALL + c], acc[b]);
    }

    __shared__ float red[8][B_];
    #pragma unroll
    for (int b = 0; b < B_; b++) {
        float v = acc[b];
        #pragma unroll
        for (int o = 16; o; o >>= 1) v += __shfl_xor_sync(0xffffffffu, v, o);
        acc[b] = v;
    }
    if (lane == 0)
        #pragma unroll
        for (int b = 0; b < B_; b++) red[warp][b] = acc[b];
    __syncthreads();
    if (tid < B_) {
        float s = 0.f;
        #pragma unroll
        for (int w = 0; w < 8; w++) s += red[w][tid];
        out[(size_t)tid * NK + k] = s;
    }
}

// ---------------------------------------------------------------------------
extern "C" void kernel_launch(void* const* d_in, const int* in_sizes, int n_in,
                              void* d_out, int out_size) {
    const float* l3  = (const float*)d_in[0];
    const float* l4  = (const float*)d_in[1];
    const float* Wl  = (const float*)d_in[2];
    const float* Wc  = (const float*)d_in[3];
    const float* mod = (const float*)d_in[4];
    float* out = (float*)d_out;

    k_asq<<<NL, 256>>>(Wl);
    k_ab<<<dim3(NCH4 + NCH3, B_), 196>>>(l3, l4, Wl);
    k_red<<<(B_ * NL * HW4 + 63) / 64, 64>>>();
    k_softmax<<<(B_ * HW) / 32, 288>>>(out);
    k_mapsdown<<<(B_ * NL * HW4 + 63) / 64, 64>>>(out);
    k_feat<<<dim3(24, B_), 256>>>(l3, l4, mod, out);
    k_cls<<<NK, 256>>>(Wc, out);
}